// round 14
// baseline (speedup 1.0000x reference)
#include <cuda_runtime.h>
#include <cuda_bf16.h>
#include <math.h>
#include <stdint.h>

#define BATCH 4
#define HW 16384
#define HH 128
#define WW 128
#define OFFC 18
#define CMID 128
#define EPS 1e-5f
#define OFFSPLIT (BATCH * OFFC * HW)

#define SWZ128(o) ((o) ^ (((o) >> 3) & 0x70))

__device__ __forceinline__ uint32_t smem_u32(const void* p) {
    uint32_t a;
    asm("{ .reg .u64 t; cvta.to.shared.u64 t, %1; cvt.u32.u64 %0, t; }" : "=r"(a) : "l"(p));
    return a;
}
__device__ __forceinline__ void ldmx4(uint32_t* r, uint32_t addr) {
    asm volatile("ldmatrix.sync.aligned.m8n8.x4.shared.b16 {%0,%1,%2,%3}, [%4];"
                 : "=r"(r[0]), "=r"(r[1]), "=r"(r[2]), "=r"(r[3]) : "r"(addr));
}
__device__ __forceinline__ void mma16816(float* d, const uint32_t* a, const uint32_t* b) {
    asm volatile(
        "mma.sync.aligned.m16n8k16.row.col.f32.bf16.bf16.f32 "
        "{%0,%1,%2,%3}, {%4,%5,%6,%7}, {%8,%9}, {%0,%1,%2,%3};"
        : "+f"(d[0]), "+f"(d[1]), "+f"(d[2]), "+f"(d[3])
        : "r"(a[0]), "r"(a[1]), "r"(a[2]), "r"(a[3]), "r"(b[0]), "r"(b[1]));
}
__device__ __forceinline__ void bar_sync(int id, int cnt) {
    asm volatile("bar.sync %0, %1;" :: "r"(id), "r"(cnt) : "memory");
}
__device__ __forceinline__ void bar_arrive(int id, int cnt) {
    asm volatile("bar.arrive %0, %1;" :: "r"(id), "r"(cnt) : "memory");
}

// ---------------- scratch (device globals) ----------------
__device__ float g_off[8 * OFFSPLIT];            // 8-way split offset partials
__device__ float g_t1 [BATCH * CMID * HW];
__device__ float g_t2 [BATCH * CMID * HW];
__device__ float g_stats[2 * CMID];
__device__ float g_part[1024 * 256];             // per-block (sum, sumsq) partials
__device__ __nv_bfloat16 g_wsw1[2 * 18 * 128 * 32];
__device__ __nv_bfloat16 g_wsw2[2 * 36 * 128 * 32];

// w[o][c][k] -> wsw[plane][ch][o][e], kk = ch*32+e = k*C + c
__global__ void prep_w_sw(const float* __restrict__ w,
                          __nv_bfloat16* __restrict__ wsw, int C) {
    const int CK = C * 9;
    const int NCH = CK / 32;
    int i = blockIdx.x * blockDim.x + threadIdx.x;
    if (i >= 2 * CK * 128) return;
    int plane = i / (CK * 128);
    int rem   = i - plane * CK * 128;
    int ch = rem / (128 * 32);
    int r2 = rem - ch * 128 * 32;
    int o  = r2 >> 5;
    int e  = r2 & 31;
    int kk = ch * 32 + e;
    int k = kk / C, c = kk - k * C;
    float v = w[(o * C + c) * 9 + k];
    __nv_bfloat16 h = __float2bfloat16(v);
    __nv_bfloat16 res = plane ? __float2bfloat16(v - __bfloat162float(h)) : h;
    wsw[((size_t)(plane * NCH + ch) * 128 + o) * 32 + e] = res;
}

// ---------------- 3x3 offset conv: 6 oc per block, channel-split x8 ----------------
// Loads restructured: h is warp-uniform (uniform y-branch); interior 4 taps as one
// aligned float4; only the two edge taps predicated.
template<int C, bool BNIN>
__global__ void __launch_bounds__(256)
conv_off6(const float* __restrict__ x, const float* __restrict__ w,
          const float* __restrict__ bias, const float* __restrict__ stats,
          float* __restrict__ out)
{
    constexpr int CH = C / 8;
    extern __shared__ float ws[];             // [6][CH][9]
    const int b  = blockIdx.y >> 3;
    const int s  = blockIdx.y & 7;
    const int g  = blockIdx.z;
    for (int i = threadIdx.x; i < 6 * CH * 9; i += 256) {
        int oc = i / (CH * 9);
        int r  = i - oc * (CH * 9);
        ws[i] = w[((g * 6 + oc) * C + s * CH) * 9 + r];
    }
    __syncthreads();

    const int quad = blockIdx.x * 256 + threadIdx.x;
    const int h  = quad >> 5;                 // warp-uniform
    const int w0 = (quad & 31) << 2;
    const bool has_l = (w0 > 0);
    const bool has_r = (w0 < 124);

    const float* xb = x + ((size_t)b * C + s * CH) * HW;
    float acc[6][4];
    #pragma unroll
    for (int oc = 0; oc < 6; oc++) {
        float bv = s ? 0.f : bias[g * 6 + oc];
        acc[oc][0] = bv; acc[oc][1] = bv; acc[oc][2] = bv; acc[oc][3] = bv;
    }

    for (int c = 0; c < CH; c++) {
        const float* xc = xb + c * HW;
        float sc = 1.f, sh = 0.f;
        if (BNIN) {
            int cg = s * CH + c;
            sc = __ldg(&stats[cg]);
            sh = __ldg(&stats[CMID + cg]);
        }
        float r[3][6];
        #pragma unroll
        for (int dy = 0; dy < 3; dy++) {
            int y = h - 1 + dy;
            if (y >= 0 && y < HH) {           // uniform branch
                const float* row = xc + y * WW + w0;
                float4 m = *(const float4*)row;
                float lf = has_l ? row[-1] : 0.f;
                float rt = has_r ? row[4]  : 0.f;
                if (BNIN) {
                    m.x = fmaxf(fmaf(m.x, sc, sh), 0.f);
                    m.y = fmaxf(fmaf(m.y, sc, sh), 0.f);
                    m.z = fmaxf(fmaf(m.z, sc, sh), 0.f);
                    m.w = fmaxf(fmaf(m.w, sc, sh), 0.f);
                    lf = has_l ? fmaxf(fmaf(lf, sc, sh), 0.f) : 0.f;
                    rt = has_r ? fmaxf(fmaf(rt, sc, sh), 0.f) : 0.f;
                }
                r[dy][0] = lf;  r[dy][1] = m.x; r[dy][2] = m.y;
                r[dy][3] = m.z; r[dy][4] = m.w; r[dy][5] = rt;
            } else {
                #pragma unroll
                for (int dx = 0; dx < 6; dx++) r[dy][dx] = 0.f;
            }
        }
        #pragma unroll
        for (int oc = 0; oc < 6; oc++) {
            const float* wc = ws + (oc * CH + c) * 9;
            #pragma unroll
            for (int dy = 0; dy < 3; dy++) {
                #pragma unroll
                for (int kx = 0; kx < 3; kx++) {
                    float wv = wc[dy * 3 + kx];
                    acc[oc][0] += wv * r[dy][kx + 0];
                    acc[oc][1] += wv * r[dy][kx + 1];
                    acc[oc][2] += wv * r[dy][kx + 2];
                    acc[oc][3] += wv * r[dy][kx + 3];
                }
            }
        }
    }
    float* outp = out + (size_t)s * OFFSPLIT;
    #pragma unroll
    for (int oc = 0; oc < 6; oc++) {
        float4 v = make_float4(acc[oc][0], acc[oc][1], acc[oc][2], acc[oc][3]);
        *reinterpret_cast<float4*>(
            &outp[((size_t)b * OFFC + g * 6 + oc) * HW + h * WW + w0]) = v;
    }
}

// ---------------- deformable conv: warp-specialized mma.sync bf16x3, 64-px tiles ----------------
// 512 threads: warps 0-7 consumers (tile 64px x 128o), warps 8-15 producers.
// Grid 1024 tiles (6.9 waves) kills the wave-quantization tail of 128-px tiles.
// 4 chunk-slots in two tile-sets: A 64x128B (hi/lo) + B 128x128B (hi/lo), SW128.
#define TSET    49152
#define AHI_O   0
#define ALO_O   8192
#define BHI_O   16384
#define BLO_O   32768
#define OFF_MI  (2 * TSET)                      // 98304: ushort4[9*64] = 4608
#define OFF_MW  (OFF_MI + 4608)                 // 102912: float4[9*64] = 9216
#define OFF_ST  (OFF_MW + 9216)                 // 112128: 256 floats BN stats
#define SMEM_TOTAL (OFF_ST + 1024)              // 113152

template<int C, bool BNIN>
__global__ void __launch_bounds__(512, 1)
deform_mma(const float* __restrict__ x, const float* __restrict__ offs,
           const float* __restrict__ stats,
           const __nv_bfloat16* __restrict__ wsw,
           const float* __restrict__ bias, float* __restrict__ out,
           float* __restrict__ part)
{
    constexpr int CK  = C * 9;
    constexpr int NCH = CK / 32;
    extern __shared__ __align__(1024) char smem[];
    const uint32_t sbase = smem_u32(smem);
    const int tid = threadIdx.x, wid = tid >> 5, l = tid & 31;
    const int b = blockIdx.y;
    const int pbase = blockIdx.x * 64;          // 64-px tile

    const float* xb   = x + (size_t)b * C * HW;
    const float* offb = offs + (size_t)b * OFFC * HW;

    ushort4* Mi = (ushort4*)(smem + OFF_MI);
    float4*  Mw = (float4*)(smem + OFF_MW);
    float*   sst = (float*)(smem + OFF_ST);

    if (BNIN && tid < 256) sst[tid] = stats[tid];

    // bilinear metadata: 9 k x 64 px (8 split offsets summed)
    for (int i = tid; i < 9 * 64; i += 512) {
        int k = i >> 6, wl = i & 63;
        int pixel = pbase + wl;
        int hrow = pixel >> 7, wcol = pixel & 127;
        const float* oy_p = offb + (2 * k) * HW + pixel;
        const float* ox_p = offb + (2 * k + 1) * HW + pixel;
        float offy = 0.f, offx = 0.f;
        #pragma unroll
        for (int s = 0; s < 8; s++) {
            offy += oy_p[(size_t)s * OFFSPLIT];
            offx += ox_p[(size_t)s * OFFSPLIT];
        }
        float py = (float)(hrow - 1 + k / 3) + offy;
        float px_ = (float)(wcol - 1 + (k - (k / 3) * 3)) + offx;
        float fy = floorf(py), fx = floorf(px_);
        int y0 = (int)fy, x0 = (int)fx;
        float wy1 = py - fy, wx1 = px_ - fx;
        float wy0 = 1.f - wy1, wx0 = 1.f - wx1;
        bool y0v = ((unsigned)y0 < 128u);
        bool y1v = ((unsigned)(y0 + 1) < 128u);
        bool x0v = ((unsigned)x0 < 128u);
        bool x1v = ((unsigned)(x0 + 1) < 128u);
        int y0c = min(max(y0, 0), 127), y1c = min(max(y0 + 1, 0), 127);
        int x0c = min(max(x0, 0), 127), x1c = min(max(x0 + 1, 0), 127);
        Mw[i] = make_float4(y0v && x0v ? wy0 * wx0 : 0.f,
                            y0v && x1v ? wy0 * wx1 : 0.f,
                            y1v && x0v ? wy1 * wx0 : 0.f,
                            y1v && x1v ? wy1 * wx1 : 0.f);
        Mi[i] = make_ushort4((unsigned short)(y0c * 128 + x0c),
                             (unsigned short)(y0c * 128 + x1c),
                             (unsigned short)(y1c * 128 + x0c),
                             (unsigned short)(y1c * 128 + x1c));
    }
    __syncthreads();

    if (wid >= 8) {
        // ================= PRODUCER =================
        const int ptid = tid - 256;
        const int px = ptid & 63;               // tile-local pixel
        const int cg = ptid >> 6;               // 0..3: 8-channel group
        for (int ch = 0; ch < NCH; ++ch) {
            const int slot = ch & 3;
            if (ch >= 4) bar_sync(5 + slot, 512);
            char* ts = smem + (slot >> 1) * TSET;
            const int h64 = (slot & 1) * 64;
            // B: coalesced copy of pre-swizzled chunk image (128 o-rows)
            {
                const int o = ptid & 127, plane = ptid >> 7;
                const uint4* src = (const uint4*)(wsw +
                    ((size_t)(plane * NCH + ch) * 128 + o) * 32);
                uint4 v0 = src[0], v1 = src[1], v2 = src[2], v3 = src[3];
                char* bt = ts + (plane ? BLO_O : BHI_O);
                int base = o * 128 + h64;
                *(uint4*)(bt + SWZ128(base))      = v0;
                *(uint4*)(bt + SWZ128(base + 16)) = v1;
                *(uint4*)(bt + SWZ128(base + 32)) = v2;
                *(uint4*)(bt + SWZ128(base + 48)) = v3;
            }
            // A: bilinear gather, 8 channels per thread
            {
                int k, c0;
                if (C == 64) { k = ch >> 1; c0 = (ch & 1) * 32; }
                else         { k = ch >> 2; c0 = (ch & 3) * 32; }
                ushort4 mi = Mi[k * 64 + px];
                float4  mw = Mw[k * 64 + px];
                const int cbase = c0 + cg * 8;
                const float* xc = xb + (size_t)cbase * HW;
                uint32_t hp[4], lp[4];
                #pragma unroll
                for (int g = 0; g < 2; ++g) {
                    float s[4];
                    #pragma unroll
                    for (int cc = 0; cc < 4; ++cc) {
                        const float* p = xc + (size_t)(g * 4 + cc) * HW;
                        float t0 = p[mi.x], t1 = p[mi.y], t2 = p[mi.z], t3 = p[mi.w];
                        if (BNIN) {
                            int chn = cbase + g * 4 + cc;
                            float sc = sst[chn], sh = sst[CMID + chn];
                            t0 = fmaxf(fmaf(t0, sc, sh), 0.f);
                            t1 = fmaxf(fmaf(t1, sc, sh), 0.f);
                            t2 = fmaxf(fmaf(t2, sc, sh), 0.f);
                            t3 = fmaxf(fmaf(t3, sc, sh), 0.f);
                        }
                        s[cc] = mw.x * t0 + mw.y * t1 + mw.z * t2 + mw.w * t3;
                    }
                    #pragma unroll
                    for (int q = 0; q < 2; ++q) {
                        float s0 = s[2 * q], s1 = s[2 * q + 1];
                        uint32_t hh;
                        asm("cvt.rn.bf16x2.f32 %0, %1, %2;" : "=r"(hh) : "f"(s1), "f"(s0));
                        float h0 = __uint_as_float(hh << 16);
                        float h1 = __uint_as_float(hh & 0xFFFF0000u);
                        float l0 = s0 - h0, l1 = s1 - h1;
                        uint32_t ll;
                        asm("cvt.rn.bf16x2.f32 %0, %1, %2;" : "=r"(ll) : "f"(l1), "f"(l0));
                        hp[g * 2 + q] = hh;
                        lp[g * 2 + q] = ll;
                    }
                }
                int base = px * 128 + h64 + cg * 16;
                *(uint4*)(ts + AHI_O + SWZ128(base)) = make_uint4(hp[0], hp[1], hp[2], hp[3]);
                *(uint4*)(ts + ALO_O + SWZ128(base)) = make_uint4(lp[0], lp[1], lp[2], lp[3]);
            }
            bar_arrive(1 + slot, 512);
        }
        return;   // producers exit; epilogue is consumer-only
    }

    // ================= CONSUMER =================
    const int mrow = (wid & 1) * 32;
    const int ncol = (wid >> 1) * 32;

    uint32_t a_base[2], a_x[2];
    {
        int row = mrow + (l & 15);
        #pragma unroll
        for (int i = 0; i < 2; i++) {
            int r = row + i * 16;
            a_base[i] = r * 128;
            a_x[i]    = (r & 7) << 4;
        }
    }
    const uint32_t a_k = (l >> 4) * 16;
    uint32_t b_base[2], b_x[2];
    {
        int row = ncol + (l & 7) + ((l >> 4) & 1) * 8;
        #pragma unroll
        for (int jp = 0; jp < 2; jp++) {
            int r = row + jp * 16;
            b_base[jp] = r * 128;
            b_x[jp]    = (r & 7) << 4;
        }
    }
    const uint32_t b_k = ((l >> 3) & 1) * 16;

    float acc[2][4][4];
    #pragma unroll
    for (int i = 0; i < 2; i++)
        #pragma unroll
        for (int j = 0; j < 4; j++)
            #pragma unroll
            for (int q = 0; q < 4; q++) acc[i][j][q] = 0.f;

    for (int ch = 0; ch < NCH; ++ch) {
        const int slot = ch & 3;
        bar_sync(1 + slot, 512);
        const uint32_t ts = sbase + (slot >> 1) * TSET;
        const uint32_t sAh = ts + AHI_O, sAl = ts + ALO_O;
        const uint32_t sBh = ts + BHI_O, sBl = ts + BLO_O;
        const uint32_t h64 = (slot & 1) * 64;
        #pragma unroll
        for (int ks = 0; ks < 2; ++ks) {
            const uint32_t ka = h64 + ks * 32 + a_k;
            const uint32_t kb = h64 + ks * 32 + b_k;
            uint32_t ah[2][4], al[2][4], bh[2][4], bl[2][4];
            #pragma unroll
            for (int i = 0; i < 2; i++)
                ldmx4(ah[i], sAh + a_base[i] + (ka ^ a_x[i]));
            #pragma unroll
            for (int jp = 0; jp < 2; jp++)
                ldmx4(bh[jp], sBh + b_base[jp] + (kb ^ b_x[jp]));
            #pragma unroll
            for (int i = 0; i < 2; i++)
                #pragma unroll
                for (int jp = 0; jp < 2; jp++) {
                    mma16816(acc[i][jp * 2],     ah[i], &bh[jp][0]);
                    mma16816(acc[i][jp * 2 + 1], ah[i], &bh[jp][2]);
                }
            #pragma unroll
            for (int jp = 0; jp < 2; jp++)
                ldmx4(bl[jp], sBl + b_base[jp] + (kb ^ b_x[jp]));
            #pragma unroll
            for (int i = 0; i < 2; i++)
                #pragma unroll
                for (int jp = 0; jp < 2; jp++) {
                    mma16816(acc[i][jp * 2],     ah[i], &bl[jp][0]);
                    mma16816(acc[i][jp * 2 + 1], ah[i], &bl[jp][2]);
                }
            #pragma unroll
            for (int i = 0; i < 2; i++)
                ldmx4(al[i], sAl + a_base[i] + (ka ^ a_x[i]));
            #pragma unroll
            for (int i = 0; i < 2; i++)
                #pragma unroll
                for (int jp = 0; jp < 2; jp++) {
                    mma16816(acc[i][jp * 2],     al[i], &bh[jp][0]);
                    mma16816(acc[i][jp * 2 + 1], al[i], &bh[jp][2]);
                }
        }
        bar_arrive(5 + slot, 512);
    }

    // ---- epilogue (consumers only): store + per-channel BN partials ----
    float* ob = out + (size_t)b * 128 * HW + pbase;
    const int m0 = mrow + (l >> 2);
    float ss[4][2], sq[4][2];
    #pragma unroll
    for (int j = 0; j < 4; j++) { ss[j][0]=ss[j][1]=sq[j][0]=sq[j][1]=0.f; }
    #pragma unroll
    for (int j = 0; j < 4; j++) {
        int n0 = ncol + j * 8 + 2 * (l & 3);
        float bi0 = __ldg(&bias[n0]), bi1 = __ldg(&bias[n0 + 1]);
        #pragma unroll
        for (int i = 0; i < 2; i++) {
            int m = m0 + i * 16;
            float v0 = acc[i][j][0] + bi0;
            float v1 = acc[i][j][1] + bi1;
            float v2 = acc[i][j][2] + bi0;
            float v3 = acc[i][j][3] + bi1;
            ob[(size_t)n0       * HW + m]     = v0;
            ob[(size_t)(n0 + 1) * HW + m]     = v1;
            ob[(size_t)n0       * HW + m + 8] = v2;
            ob[(size_t)(n0 + 1) * HW + m + 8] = v3;
            ss[j][0] += v0 + v2;  sq[j][0] += v0 * v0 + v2 * v2;
            ss[j][1] += v1 + v3;  sq[j][1] += v1 * v1 + v3 * v3;
        }
    }
    #pragma unroll
    for (int j = 0; j < 4; j++)
        #pragma unroll
        for (int low = 0; low < 2; low++)
            #pragma unroll
            for (int m = 4; m <= 16; m <<= 1) {
                ss[j][low] += __shfl_xor_sync(0xFFFFFFFFu, ss[j][low], m);
                sq[j][low] += __shfl_xor_sync(0xFFFFFFFFu, sq[j][low], m);
            }
    float* spart = (float*)(smem + OFF_MI);    // Mi dead (producers exited)
    if (l < 4) {
        #pragma unroll
        for (int j = 0; j < 4; j++)
            #pragma unroll
            for (int low = 0; low < 2; low++) {
                spart[wid * 64 + j * 16 + l * 4 + low * 2 + 0] = ss[j][low];
                spart[wid * 64 + j * 16 + l * 4 + low * 2 + 1] = sq[j][low];
            }
    }
    bar_sync(9, 256);
    {
        int ch = tid >> 1, st = tid & 1;
        int slice = ch >> 5, co = ch & 31;
        int j = co >> 3, r = (co >> 1) & 3, low = co & 1;
        int idx = j * 16 + r * 4 + low * 2 + st;
        float v = spart[(2 * slice) * 64 + idx] + spart[(2 * slice + 1) * 64 + idx];
        int bid = blockIdx.y * gridDim.x + blockIdx.x;
        part[bid * 256 + tid] = v;
    }
}

// ---------------- BN finalize: 1024 block-partials -> scale/shift (128 blocks) ----------------
__global__ void bn_finalize(const float* __restrict__ part,
                            const float* __restrict__ gamma,
                            const float* __restrict__ beta,
                            float* __restrict__ stats)
{
    const int c = blockIdx.x;
    const int t = threadIdx.x;
    float sum = 0.f, sq = 0.f;
    #pragma unroll
    for (int r = 0; r < 4; r++) {
        sum += part[(size_t)(t + r * 256) * 256 + 2 * c];
        sq  += part[(size_t)(t + r * 256) * 256 + 2 * c + 1];
    }
    __shared__ float s1[256], s2[256];
    s1[t] = sum; s2[t] = sq;
    __syncthreads();
    for (int st = 128; st > 0; st >>= 1) {
        if (t < st) { s1[t] += s1[t + st]; s2[t] += s2[t + st]; }
        __syncthreads();
    }
    if (t == 0) {
        const float n = (float)(BATCH * HW);
        float mean = s1[0] / n;
        float var  = s2[0] / n - mean * mean;
        float inv  = rsqrtf(var + EPS);
        float sc   = gamma[c] * inv;
        stats[c]        = sc;
        stats[CMID + c] = beta[c] - mean * sc;
    }
}

// ---------------- BN apply + ReLU (final stage only) ----------------
__global__ void bn_apply_kernel(const float* __restrict__ in,
                                const float* __restrict__ stats,
                                float* __restrict__ out)
{
    const int total4 = BATCH * CMID * HW / 4;
    int i = blockIdx.x * blockDim.x + threadIdx.x;
    if (i >= total4) return;
    int e = i * 4;
    int c = (e >> 14) & 127;
    float sc = stats[c], sh = stats[CMID + c];
    float4 v = reinterpret_cast<const float4*>(in)[i];
    v.x = fmaxf(v.x * sc + sh, 0.f);
    v.y = fmaxf(v.y * sc + sh, 0.f);
    v.z = fmaxf(v.z * sc + sh, 0.f);
    v.w = fmaxf(v.w * sc + sh, 0.f);
    reinterpret_cast<float4*>(out)[i] = v;
}

extern "C" void kernel_launch(void* const* d_in, const int* in_sizes, int n_in,
                              void* d_out, int out_size)
{
    const float* x      = (const float*)d_in[0];
    const float* w_off1 = (const float*)d_in[1];
    const float* b_off1 = (const float*)d_in[2];
    const float* w1     = (const float*)d_in[3];
    const float* b1     = (const float*)d_in[4];
    const float* g1     = (const float*)d_in[5];
    const float* be1    = (const float*)d_in[6];
    const float* w_off2 = (const float*)d_in[7];
    const float* b_off2 = (const float*)d_in[8];
    const float* w2     = (const float*)d_in[9];
    const float* b2     = (const float*)d_in[10];
    const float* g2     = (const float*)d_in[11];
    const float* be2    = (const float*)d_in[12];
    float* out = (float*)d_out;

    float *off, *t1, *t2, *stats, *part;
    __nv_bfloat16 *wsw1, *wsw2;
    cudaGetSymbolAddress((void**)&off,   g_off);
    cudaGetSymbolAddress((void**)&t1,    g_t1);
    cudaGetSymbolAddress((void**)&t2,    g_t2);
    cudaGetSymbolAddress((void**)&stats, g_stats);
    cudaGetSymbolAddress((void**)&part,  g_part);
    cudaGetSymbolAddress((void**)&wsw1,  g_wsw1);
    cudaGetSymbolAddress((void**)&wsw2,  g_wsw2);

    cudaFuncSetAttribute((const void*)deform_mma<64, false>,
                         cudaFuncAttributeMaxDynamicSharedMemorySize, SMEM_TOTAL);
    cudaFuncSetAttribute((const void*)deform_mma<128, true>,
                         cudaFuncAttributeMaxDynamicSharedMemorySize, SMEM_TOTAL);

    prep_w_sw<<<(2 * 576 * 128 + 255) / 256, 256>>>(w1, wsw1, 64);
    prep_w_sw<<<(2 * 1152 * 128 + 255) / 256, 256>>>(w2, wsw2, 128);

    // stage 1
    conv_off6<64, false><<<dim3(16, BATCH * 8, 3), 256, 6 * 8 * 9 * 4>>>(
        x, w_off1, b_off1, stats, off);
    deform_mma<64, false><<<dim3(256, BATCH), 512, SMEM_TOTAL>>>(
        x, off, stats, wsw1, b1, t1, part);
    bn_finalize<<<128, 256>>>(part, g1, be1, stats);

    // stage 2 (consumers apply stage-1 BN+ReLU inline on raw t1)
    conv_off6<128, true><<<dim3(16, BATCH * 8, 3), 256, 6 * 16 * 9 * 4>>>(
        t1, w_off2, b_off2, stats, off);
    deform_mma<128, true><<<dim3(256, BATCH), 512, SMEM_TOTAL>>>(
        t1, off, stats, wsw2, b2, t2, part);
    bn_finalize<<<128, 256>>>(part, g2, be2, stats);
    bn_apply_kernel<<<(BATCH * CMID * HW / 4 + 255) / 256, 256>>>(t2, stats, out);
}

// round 15
// speedup vs baseline: 1.1088x; 1.1088x over previous
#include <cuda_runtime.h>
#include <cuda_bf16.h>
#include <math.h>
#include <stdint.h>

#define BATCH 4
#define HW 16384
#define HH 128
#define WW 128
#define OFFC 18
#define CMID 128
#define EPS 1e-5f
#define OFFSPLIT (BATCH * OFFC * HW)

#define SWZ128(o) ((o) ^ (((o) >> 3) & 0x70))

__device__ __forceinline__ uint32_t smem_u32(const void* p) {
    uint32_t a;
    asm("{ .reg .u64 t; cvta.to.shared.u64 t, %1; cvt.u32.u64 %0, t; }" : "=r"(a) : "l"(p));
    return a;
}
__device__ __forceinline__ void ldmx4(uint32_t* r, uint32_t addr) {
    asm volatile("ldmatrix.sync.aligned.m8n8.x4.shared.b16 {%0,%1,%2,%3}, [%4];"
                 : "=r"(r[0]), "=r"(r[1]), "=r"(r[2]), "=r"(r[3]) : "r"(addr));
}
__device__ __forceinline__ void mma16816(float* d, const uint32_t* a, const uint32_t* b) {
    asm volatile(
        "mma.sync.aligned.m16n8k16.row.col.f32.bf16.bf16.f32 "
        "{%0,%1,%2,%3}, {%4,%5,%6,%7}, {%8,%9}, {%0,%1,%2,%3};"
        : "+f"(d[0]), "+f"(d[1]), "+f"(d[2]), "+f"(d[3])
        : "r"(a[0]), "r"(a[1]), "r"(a[2]), "r"(a[3]), "r"(b[0]), "r"(b[1]));
}
__device__ __forceinline__ void bar_sync(int id, int cnt) {
    asm volatile("bar.sync %0, %1;" :: "r"(id), "r"(cnt) : "memory");
}
__device__ __forceinline__ void bar_arrive(int id, int cnt) {
    asm volatile("bar.arrive %0, %1;" :: "r"(id), "r"(cnt) : "memory");
}

// ---------------- scratch (device globals) ----------------
__device__ float g_off[8 * OFFSPLIT];            // 8-way split offset partials
__device__ float g_t1 [BATCH * CMID * HW];
__device__ float g_t2 [BATCH * CMID * HW];
__device__ float g_stats[2 * CMID];
__device__ float g_part[512 * 256];              // per-block (sum, sumsq) partials
__device__ __nv_bfloat16 g_wsw1[2 * 18 * 128 * 32];
__device__ __nv_bfloat16 g_wsw2[2 * 36 * 128 * 32];

// w[o][c][k] -> wsw[plane][ch][o][e], kk = ch*32+e = k*C + c
__global__ void prep_w_sw(const float* __restrict__ w,
                          __nv_bfloat16* __restrict__ wsw, int C) {
    const int CK = C * 9;
    const int NCH = CK / 32;
    int i = blockIdx.x * blockDim.x + threadIdx.x;
    if (i >= 2 * CK * 128) return;
    int plane = i / (CK * 128);
    int rem   = i - plane * CK * 128;
    int ch = rem / (128 * 32);
    int r2 = rem - ch * 128 * 32;
    int o  = r2 >> 5;
    int e  = r2 & 31;
    int kk = ch * 32 + e;
    int k = kk / C, c = kk - k * C;
    float v = w[(o * C + c) * 9 + k];
    __nv_bfloat16 h = __float2bfloat16(v);
    __nv_bfloat16 res = plane ? __float2bfloat16(v - __bfloat162float(h)) : h;
    wsw[((size_t)(plane * NCH + ch) * 128 + o) * 32 + e] = res;
}

// ---------------- 3x3 offset conv: 6 oc per block, channel-split x8 ----------------
// Loads restructured: h is warp-uniform (uniform y-branch); interior 4 taps as one
// aligned float4; only the two edge taps predicated.
template<int C, bool BNIN>
__global__ void __launch_bounds__(256)
conv_off6(const float* __restrict__ x, const float* __restrict__ w,
          const float* __restrict__ bias, const float* __restrict__ stats,
          float* __restrict__ out)
{
    constexpr int CH = C / 8;
    extern __shared__ float ws[];             // [6][CH][9]
    const int b  = blockIdx.y >> 3;
    const int s  = blockIdx.y & 7;
    const int g  = blockIdx.z;
    for (int i = threadIdx.x; i < 6 * CH * 9; i += 256) {
        int oc = i / (CH * 9);
        int r  = i - oc * (CH * 9);
        ws[i] = w[((g * 6 + oc) * C + s * CH) * 9 + r];
    }
    __syncthreads();

    const int quad = blockIdx.x * 256 + threadIdx.x;
    const int h  = quad >> 5;                 // warp-uniform
    const int w0 = (quad & 31) << 2;
    const bool has_l = (w0 > 0);
    const bool has_r = (w0 < 124);

    const float* xb = x + ((size_t)b * C + s * CH) * HW;
    float acc[6][4];
    #pragma unroll
    for (int oc = 0; oc < 6; oc++) {
        float bv = s ? 0.f : bias[g * 6 + oc];
        acc[oc][0] = bv; acc[oc][1] = bv; acc[oc][2] = bv; acc[oc][3] = bv;
    }

    for (int c = 0; c < CH; c++) {
        const float* xc = xb + c * HW;
        float sc = 1.f, sh = 0.f;
        if (BNIN) {
            int cg = s * CH + c;
            sc = __ldg(&stats[cg]);
            sh = __ldg(&stats[CMID + cg]);
        }
        float r[3][6];
        #pragma unroll
        for (int dy = 0; dy < 3; dy++) {
            int y = h - 1 + dy;
            if (y >= 0 && y < HH) {           // uniform branch
                const float* row = xc + y * WW + w0;
                float4 m = *(const float4*)row;
                float lf = has_l ? row[-1] : 0.f;
                float rt = has_r ? row[4]  : 0.f;
                if (BNIN) {
                    m.x = fmaxf(fmaf(m.x, sc, sh), 0.f);
                    m.y = fmaxf(fmaf(m.y, sc, sh), 0.f);
                    m.z = fmaxf(fmaf(m.z, sc, sh), 0.f);
                    m.w = fmaxf(fmaf(m.w, sc, sh), 0.f);
                    lf = has_l ? fmaxf(fmaf(lf, sc, sh), 0.f) : 0.f;
                    rt = has_r ? fmaxf(fmaf(rt, sc, sh), 0.f) : 0.f;
                }
                r[dy][0] = lf;  r[dy][1] = m.x; r[dy][2] = m.y;
                r[dy][3] = m.z; r[dy][4] = m.w; r[dy][5] = rt;
            } else {
                #pragma unroll
                for (int dx = 0; dx < 6; dx++) r[dy][dx] = 0.f;
            }
        }
        #pragma unroll
        for (int oc = 0; oc < 6; oc++) {
            const float* wc = ws + (oc * CH + c) * 9;
            #pragma unroll
            for (int dy = 0; dy < 3; dy++) {
                #pragma unroll
                for (int kx = 0; kx < 3; kx++) {
                    float wv = wc[dy * 3 + kx];
                    acc[oc][0] += wv * r[dy][kx + 0];
                    acc[oc][1] += wv * r[dy][kx + 1];
                    acc[oc][2] += wv * r[dy][kx + 2];
                    acc[oc][3] += wv * r[dy][kx + 3];
                }
            }
        }
    }
    float* outp = out + (size_t)s * OFFSPLIT;
    #pragma unroll
    for (int oc = 0; oc < 6; oc++) {
        float4 v = make_float4(acc[oc][0], acc[oc][1], acc[oc][2], acc[oc][3]);
        *reinterpret_cast<float4*>(
            &outp[((size_t)b * OFFC + g * 6 + oc) * HW + h * WW + w0]) = v;
    }
}

// ---------------- deformable conv: warp-specialized mma.sync bf16x3 (round-13) ----------------
// 512 threads: warps 0-7 consumers (MMA+epilogue), warps 8-15 producers (fills).
// 128-px tiles; 4 chunk-slots in two tile-sets (128 rows x 128B SW128, two 64B halves).
#define TSET    65536
#define AHI_O   0
#define ALO_O   16384
#define BHI_O   32768
#define BLO_O   49152
#define OFF_MI  131072                          // ushort4[9*128] = 9216
#define OFF_MW  (OFF_MI + 9 * 128 * 8)          // 140288: float4[9*128]
#define OFF_ST  (OFF_MW + 9 * 128 * 16)         // 158720: 256 floats BN stats
#define SMEM_TOTAL (OFF_ST + 1024)              // 159744

template<int C, bool BNIN>
__global__ void __launch_bounds__(512, 1)
deform_mma(const float* __restrict__ x, const float* __restrict__ offs,
           const float* __restrict__ stats,
           const __nv_bfloat16* __restrict__ wsw,
           const float* __restrict__ bias, float* __restrict__ out,
           float* __restrict__ part)
{
    constexpr int CK  = C * 9;
    constexpr int NCH = CK / 32;
    extern __shared__ __align__(1024) char smem[];
    const uint32_t sbase = smem_u32(smem);
    const int tid = threadIdx.x, wid = tid >> 5, l = tid & 31;
    const int b = blockIdx.y;
    const int pbase = blockIdx.x * 128;
    const int hrow = pbase >> 7;

    const float* xb   = x + (size_t)b * C * HW;
    const float* offb = offs + (size_t)b * OFFC * HW;

    ushort4* Mi = (ushort4*)(smem + OFF_MI);
    float4*  Mw = (float4*)(smem + OFF_MW);
    float*   sst = (float*)(smem + OFF_ST);

    if (BNIN && tid < 256) sst[tid] = stats[tid];

    // bilinear metadata: 9 k x 128 px (8 split offsets summed)
    for (int i = tid; i < 9 * 128; i += 512) {
        int k = i >> 7, wpx = i & 127;
        int pixel = pbase + wpx;
        const float* oy_p = offb + (2 * k) * HW + pixel;
        const float* ox_p = offb + (2 * k + 1) * HW + pixel;
        float offy = 0.f, offx = 0.f;
        #pragma unroll
        for (int s = 0; s < 8; s++) {
            offy += oy_p[(size_t)s * OFFSPLIT];
            offx += ox_p[(size_t)s * OFFSPLIT];
        }
        float py = (float)(hrow - 1 + k / 3) + offy;
        float px_ = (float)(wpx - 1 + (k - (k / 3) * 3)) + offx;
        float fy = floorf(py), fx = floorf(px_);
        int y0 = (int)fy, x0 = (int)fx;
        float wy1 = py - fy, wx1 = px_ - fx;
        float wy0 = 1.f - wy1, wx0 = 1.f - wx1;
        bool y0v = ((unsigned)y0 < 128u);
        bool y1v = ((unsigned)(y0 + 1) < 128u);
        bool x0v = ((unsigned)x0 < 128u);
        bool x1v = ((unsigned)(x0 + 1) < 128u);
        int y0c = min(max(y0, 0), 127), y1c = min(max(y0 + 1, 0), 127);
        int x0c = min(max(x0, 0), 127), x1c = min(max(x0 + 1, 0), 127);
        Mw[i] = make_float4(y0v && x0v ? wy0 * wx0 : 0.f,
                            y0v && x1v ? wy0 * wx1 : 0.f,
                            y1v && x0v ? wy1 * wx0 : 0.f,
                            y1v && x1v ? wy1 * wx1 : 0.f);
        Mi[i] = make_ushort4((unsigned short)(y0c * 128 + x0c),
                             (unsigned short)(y0c * 128 + x1c),
                             (unsigned short)(y1c * 128 + x0c),
                             (unsigned short)(y1c * 128 + x1c));
    }
    __syncthreads();

    if (wid >= 8) {
        // ================= PRODUCER =================
        const int ptid = tid - 256;
        const int px = ptid & 127;
        const int cg = ptid >> 7;
        for (int ch = 0; ch < NCH; ++ch) {
            const int slot = ch & 3;
            if (ch >= 4) bar_sync(5 + slot, 512);
            char* ts = smem + (slot >> 1) * TSET;
            const int h64 = (slot & 1) * 64;
            // B: coalesced copy of pre-swizzled chunk image
            {
                const int o = ptid & 127, plane = ptid >> 7;
                const uint4* src = (const uint4*)(wsw +
                    ((size_t)(plane * NCH + ch) * 128 + o) * 32);
                uint4 v0 = src[0], v1 = src[1], v2 = src[2], v3 = src[3];
                char* bt = ts + (plane ? BLO_O : BHI_O);
                int base = o * 128 + h64;
                *(uint4*)(bt + SWZ128(base))      = v0;
                *(uint4*)(bt + SWZ128(base + 16)) = v1;
                *(uint4*)(bt + SWZ128(base + 32)) = v2;
                *(uint4*)(bt + SWZ128(base + 48)) = v3;
            }
            // A: bilinear gather, 16 channels per thread
            {
                int k, c0;
                if (C == 64) { k = ch >> 1; c0 = (ch & 1) * 32; }
                else         { k = ch >> 2; c0 = (ch & 3) * 32; }
                ushort4 mi = Mi[k * 128 + px];
                float4  mw = Mw[k * 128 + px];
                const int cbase = c0 + cg * 16;
                const float* xc = xb + (size_t)cbase * HW;
                uint32_t hp[8], lp[8];
                #pragma unroll
                for (int g = 0; g < 4; ++g) {
                    float s[4];
                    #pragma unroll
                    for (int cc = 0; cc < 4; ++cc) {
                        const float* p = xc + (size_t)(g * 4 + cc) * HW;
                        float t0 = p[mi.x], t1 = p[mi.y], t2 = p[mi.z], t3 = p[mi.w];
                        if (BNIN) {
                            int chn = cbase + g * 4 + cc;
                            float sc = sst[chn], sh = sst[CMID + chn];
                            t0 = fmaxf(fmaf(t0, sc, sh), 0.f);
                            t1 = fmaxf(fmaf(t1, sc, sh), 0.f);
                            t2 = fmaxf(fmaf(t2, sc, sh), 0.f);
                            t3 = fmaxf(fmaf(t3, sc, sh), 0.f);
                        }
                        s[cc] = mw.x * t0 + mw.y * t1 + mw.z * t2 + mw.w * t3;
                    }
                    #pragma unroll
                    for (int q = 0; q < 2; ++q) {
                        float s0 = s[2 * q], s1 = s[2 * q + 1];
                        uint32_t hh;
                        asm("cvt.rn.bf16x2.f32 %0, %1, %2;" : "=r"(hh) : "f"(s1), "f"(s0));
                        float h0 = __uint_as_float(hh << 16);
                        float h1 = __uint_as_float(hh & 0xFFFF0000u);
                        float l0 = s0 - h0, l1 = s1 - h1;
                        uint32_t ll;
                        asm("cvt.rn.bf16x2.f32 %0, %1, %2;" : "=r"(ll) : "f"(l1), "f"(l0));
                        hp[g * 2 + q] = hh;
                        lp[g * 2 + q] = ll;
                    }
                }
                int base = px * 128 + h64 + cg * 32;
                *(uint4*)(ts + AHI_O + SWZ128(base))      = make_uint4(hp[0], hp[1], hp[2], hp[3]);
                *(uint4*)(ts + AHI_O + SWZ128(base + 16)) = make_uint4(hp[4], hp[5], hp[6], hp[7]);
                *(uint4*)(ts + ALO_O + SWZ128(base))      = make_uint4(lp[0], lp[1], lp[2], lp[3]);
                *(uint4*)(ts + ALO_O + SWZ128(base + 16)) = make_uint4(lp[4], lp[5], lp[6], lp[7]);
            }
            bar_arrive(1 + slot, 512);
        }
        return;   // producers exit; epilogue is consumer-only
    }

    // ================= CONSUMER =================
    const int mrow = (wid & 1) * 64;
    const int ncol = (wid >> 1) * 32;

    uint32_t a_base[4], a_x[4];
    {
        int row = mrow + (l & 15);
        #pragma unroll
        for (int i = 0; i < 4; i++) {
            int r = row + i * 16;
            a_base[i] = r * 128;
            a_x[i]    = (r & 7) << 4;
        }
    }
    const uint32_t a_k = (l >> 4) * 16;
    uint32_t b_base[2], b_x[2];
    {
        int row = ncol + (l & 7) + ((l >> 4) & 1) * 8;
        #pragma unroll
        for (int jp = 0; jp < 2; jp++) {
            int r = row + jp * 16;
            b_base[jp] = r * 128;
            b_x[jp]    = (r & 7) << 4;
        }
    }
    const uint32_t b_k = ((l >> 3) & 1) * 16;

    float acc[4][4][4];
    #pragma unroll
    for (int i = 0; i < 4; i++)
        #pragma unroll
        for (int j = 0; j < 4; j++)
            #pragma unroll
            for (int q = 0; q < 4; q++) acc[i][j][q] = 0.f;

    for (int ch = 0; ch < NCH; ++ch) {
        const int slot = ch & 3;
        bar_sync(1 + slot, 512);
        const uint32_t ts = sbase + (slot >> 1) * TSET;
        const uint32_t sAh = ts + AHI_O, sAl = ts + ALO_O;
        const uint32_t sBh = ts + BHI_O, sBl = ts + BLO_O;
        const uint32_t h64 = (slot & 1) * 64;
        #pragma unroll
        for (int ks = 0; ks < 2; ++ks) {
            const uint32_t ka = h64 + ks * 32 + a_k;
            const uint32_t kb = h64 + ks * 32 + b_k;
            uint32_t ah[4][4], al[4][4], bh[2][4], bl[2][4];
            #pragma unroll
            for (int i = 0; i < 4; i++)
                ldmx4(ah[i], sAh + a_base[i] + (ka ^ a_x[i]));
            #pragma unroll
            for (int jp = 0; jp < 2; jp++)
                ldmx4(bh[jp], sBh + b_base[jp] + (kb ^ b_x[jp]));
            #pragma unroll
            for (int i = 0; i < 4; i++)
                #pragma unroll
                for (int jp = 0; jp < 2; jp++) {
                    mma16816(acc[i][jp * 2],     ah[i], &bh[jp][0]);
                    mma16816(acc[i][jp * 2 + 1], ah[i], &bh[jp][2]);
                }
            #pragma unroll
            for (int jp = 0; jp < 2; jp++)
                ldmx4(bl[jp], sBl + b_base[jp] + (kb ^ b_x[jp]));
            #pragma unroll
            for (int i = 0; i < 4; i++)
                #pragma unroll
                for (int jp = 0; jp < 2; jp++) {
                    mma16816(acc[i][jp * 2],     ah[i], &bl[jp][0]);
                    mma16816(acc[i][jp * 2 + 1], ah[i], &bl[jp][2]);
                }
            #pragma unroll
            for (int i = 0; i < 4; i++)
                ldmx4(al[i], sAl + a_base[i] + (ka ^ a_x[i]));
            #pragma unroll
            for (int i = 0; i < 4; i++)
                #pragma unroll
                for (int jp = 0; jp < 2; jp++) {
                    mma16816(acc[i][jp * 2],     al[i], &bh[jp][0]);
                    mma16816(acc[i][jp * 2 + 1], al[i], &bh[jp][2]);
                }
        }
        bar_arrive(5 + slot, 512);
    }

    // ---- epilogue (consumers only): store + per-channel BN partials ----
    float* ob = out + (size_t)b * 128 * HW + pbase;
    const int m0 = mrow + (l >> 2);
    float ss[4][2], sq[4][2];
    #pragma unroll
    for (int j = 0; j < 4; j++) { ss[j][0]=ss[j][1]=sq[j][0]=sq[j][1]=0.f; }
    #pragma unroll
    for (int j = 0; j < 4; j++) {
        int n0 = ncol + j * 8 + 2 * (l & 3);
        float bi0 = __ldg(&bias[n0]), bi1 = __ldg(&bias[n0 + 1]);
        #pragma unroll
        for (int i = 0; i < 4; i++) {
            int m = m0 + i * 16;
            float v0 = acc[i][j][0] + bi0;
            float v1 = acc[i][j][1] + bi1;
            float v2 = acc[i][j][2] + bi0;
            float v3 = acc[i][j][3] + bi1;
            ob[(size_t)n0       * HW + m]     = v0;
            ob[(size_t)(n0 + 1) * HW + m]     = v1;
            ob[(size_t)n0       * HW + m + 8] = v2;
            ob[(size_t)(n0 + 1) * HW + m + 8] = v3;
            ss[j][0] += v0 + v2;  sq[j][0] += v0 * v0 + v2 * v2;
            ss[j][1] += v1 + v3;  sq[j][1] += v1 * v1 + v3 * v3;
        }
    }
    #pragma unroll
    for (int j = 0; j < 4; j++)
        #pragma unroll
        for (int low = 0; low < 2; low++)
            #pragma unroll
            for (int m = 4; m <= 16; m <<= 1) {
                ss[j][low] += __shfl_xor_sync(0xFFFFFFFFu, ss[j][low], m);
                sq[j][low] += __shfl_xor_sync(0xFFFFFFFFu, sq[j][low], m);
            }
    float* spart = (float*)(smem + OFF_MI);    // Mi dead (producers exited)
    if (l < 4) {
        #pragma unroll
        for (int j = 0; j < 4; j++)
            #pragma unroll
            for (int low = 0; low < 2; low++) {
                spart[wid * 64 + j * 16 + l * 4 + low * 2 + 0] = ss[j][low];
                spart[wid * 64 + j * 16 + l * 4 + low * 2 + 1] = sq[j][low];
            }
    }
    bar_sync(9, 256);
    {
        int ch = tid >> 1, st = tid & 1;
        int slice = ch >> 5, co = ch & 31;
        int j = co >> 3, r = (co >> 1) & 3, low = co & 1;
        int idx = j * 16 + r * 4 + low * 2 + st;
        float v = spart[(2 * slice) * 64 + idx] + spart[(2 * slice + 1) * 64 + idx];
        int bid = blockIdx.y * gridDim.x + blockIdx.x;
        part[bid * 256 + tid] = v;
    }
}

// ---------------- BN finalize: 512 block-partials -> scale/shift (128 blocks) ----------------
__global__ void bn_finalize(const float* __restrict__ part,
                            const float* __restrict__ gamma,
                            const float* __restrict__ beta,
                            float* __restrict__ stats)
{
    const int c = blockIdx.x;
    const int t = threadIdx.x;
    float sum = part[(size_t)t * 256 + 2 * c] + part[(size_t)(t + 256) * 256 + 2 * c];
    float sq  = part[(size_t)t * 256 + 2 * c + 1] + part[(size_t)(t + 256) * 256 + 2 * c + 1];
    __shared__ float s1[256], s2[256];
    s1[t] = sum; s2[t] = sq;
    __syncthreads();
    for (int st = 128; st > 0; st >>= 1) {
        if (t < st) { s1[t] += s1[t + st]; s2[t] += s2[t + st]; }
        __syncthreads();
    }
    if (t == 0) {
        const float n = (float)(BATCH * HW);
        float mean = s1[0] / n;
        float var  = s2[0] / n - mean * mean;
        float inv  = rsqrtf(var + EPS);
        float sc   = gamma[c] * inv;
        stats[c]        = sc;
        stats[CMID + c] = beta[c] - mean * sc;
    }
}

// ---------------- BN apply + ReLU (final stage only) ----------------
__global__ void bn_apply_kernel(const float* __restrict__ in,
                                const float* __restrict__ stats,
                                float* __restrict__ out)
{
    const int total4 = BATCH * CMID * HW / 4;
    int i = blockIdx.x * blockDim.x + threadIdx.x;
    if (i >= total4) return;
    int e = i * 4;
    int c = (e >> 14) & 127;
    float sc = stats[c], sh = stats[CMID + c];
    float4 v = reinterpret_cast<const float4*>(in)[i];
    v.x = fmaxf(v.x * sc + sh, 0.f);
    v.y = fmaxf(v.y * sc + sh, 0.f);
    v.z = fmaxf(v.z * sc + sh, 0.f);
    v.w = fmaxf(v.w * sc + sh, 0.f);
    reinterpret_cast<float4*>(out)[i] = v;
}

extern "C" void kernel_launch(void* const* d_in, const int* in_sizes, int n_in,
                              void* d_out, int out_size)
{
    const float* x      = (const float*)d_in[0];
    const float* w_off1 = (const float*)d_in[1];
    const float* b_off1 = (const float*)d_in[2];
    const float* w1     = (const float*)d_in[3];
    const float* b1     = (const float*)d_in[4];
    const float* g1     = (const float*)d_in[5];
    const float* be1    = (const float*)d_in[6];
    const float* w_off2 = (const float*)d_in[7];
    const float* b_off2 = (const float*)d_in[8];
    const float* w2     = (const float*)d_in[9];
    const float* b2     = (const float*)d_in[10];
    const float* g2     = (const float*)d_in[11];
    const float* be2    = (const float*)d_in[12];
    float* out = (float*)d_out;

    float *off, *t1, *t2, *stats, *part;
    __nv_bfloat16 *wsw1, *wsw2;
    cudaGetSymbolAddress((void**)&off,   g_off);
    cudaGetSymbolAddress((void**)&t1,    g_t1);
    cudaGetSymbolAddress((void**)&t2,    g_t2);
    cudaGetSymbolAddress((void**)&stats, g_stats);
    cudaGetSymbolAddress((void**)&part,  g_part);
    cudaGetSymbolAddress((void**)&wsw1,  g_wsw1);
    cudaGetSymbolAddress((void**)&wsw2,  g_wsw2);

    cudaFuncSetAttribute((const void*)deform_mma<64, false>,
                         cudaFuncAttributeMaxDynamicSharedMemorySize, SMEM_TOTAL);
    cudaFuncSetAttribute((const void*)deform_mma<128, true>,
                         cudaFuncAttributeMaxDynamicSharedMemorySize, SMEM_TOTAL);

    prep_w_sw<<<(2 * 576 * 128 + 255) / 256, 256>>>(w1, wsw1, 64);
    prep_w_sw<<<(2 * 1152 * 128 + 255) / 256, 256>>>(w2, wsw2, 128);

    // stage 1
    conv_off6<64, false><<<dim3(16, BATCH * 8, 3), 256, 6 * 8 * 9 * 4>>>(
        x, w_off1, b_off1, stats, off);
    deform_mma<64, false><<<dim3(128, BATCH), 512, SMEM_TOTAL>>>(
        x, off, stats, wsw1, b1, t1, part);
    bn_finalize<<<128, 256>>>(part, g1, be1, stats);

    // stage 2 (consumers apply stage-1 BN+ReLU inline on raw t1)
    conv_off6<128, true><<<dim3(16, BATCH * 8, 3), 256, 6 * 16 * 9 * 4>>>(
        t1, w_off2, b_off2, stats, off);
    deform_mma<128, true><<<dim3(128, BATCH), 512, SMEM_TOTAL>>>(
        t1, off, stats, wsw2, b2, t2, part);
    bn_finalize<<<128, 256>>>(part, g2, be2, stats);
    bn_apply_kernel<<<(BATCH * CMID * HW / 4 + 255) / 256, 256>>>(t2, stats, out);
}

// round 16
// speedup vs baseline: 1.1116x; 1.0025x over previous
#include <cuda_runtime.h>
#include <cuda_bf16.h>
#include <math.h>
#include <stdint.h>

#define BATCH 4
#define HW 16384
#define HH 128
#define WW 128
#define OFFC 18
#define CMID 128
#define EPS 1e-5f
#define OFFSPLIT (BATCH * OFFC * HW)

#define SWZ128(o) ((o) ^ (((o) >> 3) & 0x70))

__device__ __forceinline__ uint32_t smem_u32(const void* p) {
    uint32_t a;
    asm("{ .reg .u64 t; cvta.to.shared.u64 t, %1; cvt.u32.u64 %0, t; }" : "=r"(a) : "l"(p));
    return a;
}
__device__ __forceinline__ void ldmx4(uint32_t* r, uint32_t addr) {
    asm volatile("ldmatrix.sync.aligned.m8n8.x4.shared.b16 {%0,%1,%2,%3}, [%4];"
                 : "=r"(r[0]), "=r"(r[1]), "=r"(r[2]), "=r"(r[3]) : "r"(addr));
}
__device__ __forceinline__ void mma16816(float* d, const uint32_t* a, const uint32_t* b) {
    asm volatile(
        "mma.sync.aligned.m16n8k16.row.col.f32.bf16.bf16.f32 "
        "{%0,%1,%2,%3}, {%4,%5,%6,%7}, {%8,%9}, {%0,%1,%2,%3};"
        : "+f"(d[0]), "+f"(d[1]), "+f"(d[2]), "+f"(d[3])
        : "r"(a[0]), "r"(a[1]), "r"(a[2]), "r"(a[3]), "r"(b[0]), "r"(b[1]));
}
__device__ __forceinline__ void bar_sync(int id, int cnt) {
    asm volatile("bar.sync %0, %1;" :: "r"(id), "r"(cnt) : "memory");
}
__device__ __forceinline__ void bar_arrive(int id, int cnt) {
    asm volatile("bar.arrive %0, %1;" :: "r"(id), "r"(cnt) : "memory");
}

// ---------------- scratch (device globals) ----------------
__device__ float g_off[8 * OFFSPLIT];            // 8-way split offset partials
__device__ float g_t1 [BATCH * CMID * HW];
__device__ float g_t2 [BATCH * CMID * HW];
__device__ float g_stats[2 * CMID];
__device__ float g_part[512 * 256];              // per-block (sum, sumsq) partials
__device__ __nv_bfloat16 g_wsw1[2 * 18 * 128 * 32];
__device__ __nv_bfloat16 g_wsw2[2 * 36 * 128 * 32];

// merged weight prep: w[o][c][k] -> wsw[plane][ch][o][e], kk = ch*32+e = k*C + c
__global__ void prep_w_all(const float* __restrict__ w1, const float* __restrict__ w2,
                           __nv_bfloat16* __restrict__ wsw1,
                           __nv_bfloat16* __restrict__ wsw2) {
    const int N1 = 2 * 576 * 128;
    const int N2 = 2 * 1152 * 128;
    int i = blockIdx.x * blockDim.x + threadIdx.x;
    if (i < N1) {
        const int C = 64, CK = 576, NCH = 18;
        int plane = i / (CK * 128);
        int rem   = i - plane * CK * 128;
        int ch = rem / (128 * 32);
        int r2 = rem - ch * 128 * 32;
        int o  = r2 >> 5, e = r2 & 31;
        int kk = ch * 32 + e;
        int k = kk / C, c = kk - k * C;
        float v = w1[(o * C + c) * 9 + k];
        __nv_bfloat16 h = __float2bfloat16(v);
        wsw1[((size_t)(plane * NCH + ch) * 128 + o) * 32 + e] =
            plane ? __float2bfloat16(v - __bfloat162float(h)) : h;
    } else if (i < N1 + N2) {
        i -= N1;
        const int C = 128, CK = 1152, NCH = 36;
        int plane = i / (CK * 128);
        int rem   = i - plane * CK * 128;
        int ch = rem / (128 * 32);
        int r2 = rem - ch * 128 * 32;
        int o  = r2 >> 5, e = r2 & 31;
        int kk = ch * 32 + e;
        int k = kk / C, c = kk - k * C;
        float v = w2[(o * C + c) * 9 + k];
        __nv_bfloat16 h = __float2bfloat16(v);
        wsw2[((size_t)(plane * NCH + ch) * 128 + o) * 32 + e] =
            plane ? __float2bfloat16(v - __bfloat162float(h)) : h;
    }
}

// ---------------- 3x3 offset conv: 6 oc per block, channel-split x8 ----------------
template<int C, bool BNIN>
__global__ void __launch_bounds__(256)
conv_off6(const float* __restrict__ x, const float* __restrict__ w,
          const float* __restrict__ bias, const float* __restrict__ stats,
          float* __restrict__ out)
{
    constexpr int CH = C / 8;
    extern __shared__ float ws[];             // [6][CH][9]
    const int b  = blockIdx.y >> 3;
    const int s  = blockIdx.y & 7;
    const int g  = blockIdx.z;
    for (int i = threadIdx.x; i < 6 * CH * 9; i += 256) {
        int oc = i / (CH * 9);
        int r  = i - oc * (CH * 9);
        ws[i] = w[((g * 6 + oc) * C + s * CH) * 9 + r];
    }
    __syncthreads();

    const int quad = blockIdx.x * 256 + threadIdx.x;
    const int h  = quad >> 5;                 // warp-uniform
    const int w0 = (quad & 31) << 2;
    const bool has_l = (w0 > 0);
    const bool has_r = (w0 < 124);

    const float* xb = x + ((size_t)b * C + s * CH) * HW;
    float acc[6][4];
    #pragma unroll
    for (int oc = 0; oc < 6; oc++) {
        float bv = s ? 0.f : bias[g * 6 + oc];
        acc[oc][0] = bv; acc[oc][1] = bv; acc[oc][2] = bv; acc[oc][3] = bv;
    }

    for (int c = 0; c < CH; c++) {
        const float* xc = xb + c * HW;
        float sc = 1.f, sh = 0.f;
        if (BNIN) {
            int cg = s * CH + c;
            sc = __ldg(&stats[cg]);
            sh = __ldg(&stats[CMID + cg]);
        }
        float r[3][6];
        #pragma unroll
        for (int dy = 0; dy < 3; dy++) {
            int y = h - 1 + dy;
            if (y >= 0 && y < HH) {           // uniform branch
                const float* row = xc + y * WW + w0;
                float4 m = *(const float4*)row;
                float lf = has_l ? row[-1] : 0.f;
                float rt = has_r ? row[4]  : 0.f;
                if (BNIN) {
                    m.x = fmaxf(fmaf(m.x, sc, sh), 0.f);
                    m.y = fmaxf(fmaf(m.y, sc, sh), 0.f);
                    m.z = fmaxf(fmaf(m.z, sc, sh), 0.f);
                    m.w = fmaxf(fmaf(m.w, sc, sh), 0.f);
                    lf = has_l ? fmaxf(fmaf(lf, sc, sh), 0.f) : 0.f;
                    rt = has_r ? fmaxf(fmaf(rt, sc, sh), 0.f) : 0.f;
                }
                r[dy][0] = lf;  r[dy][1] = m.x; r[dy][2] = m.y;
                r[dy][3] = m.z; r[dy][4] = m.w; r[dy][5] = rt;
            } else {
                #pragma unroll
                for (int dx = 0; dx < 6; dx++) r[dy][dx] = 0.f;
            }
        }
        #pragma unroll
        for (int oc = 0; oc < 6; oc++) {
            const float* wc = ws + (oc * CH + c) * 9;
            #pragma unroll
            for (int dy = 0; dy < 3; dy++) {
                #pragma unroll
                for (int kx = 0; kx < 3; kx++) {
                    float wv = wc[dy * 3 + kx];
                    acc[oc][0] += wv * r[dy][kx + 0];
                    acc[oc][1] += wv * r[dy][kx + 1];
                    acc[oc][2] += wv * r[dy][kx + 2];
                    acc[oc][3] += wv * r[dy][kx + 3];
                }
            }
        }
    }
    float* outp = out + (size_t)s * OFFSPLIT;
    #pragma unroll
    for (int oc = 0; oc < 6; oc++) {
        float4 v = make_float4(acc[oc][0], acc[oc][1], acc[oc][2], acc[oc][3]);
        *reinterpret_cast<float4*>(
            &outp[((size_t)b * OFFC + g * 6 + oc) * HW + h * WW + w0]) = v;
    }
}

// ---------------- deformable conv: warp-specialized mma.sync bf16x3 ----------------
// 512 threads: warps 0-7 consumers, warps 8-15 producers. 2-slot ring: ONE 64KB
// tile-set, the two 64B row-halves are the slots. smem 94KB -> L1D ~134KB so the
// in-flight bilinear-gather working set now fits L1 (the 160KB-smem config left
// only 68KB and thrashed). Producers are the slow side, so depth 2 == depth 4.
#define AHI_O   0
#define ALO_O   16384
#define BHI_O   32768
#define BLO_O   49152
#define OFF_MI  65536                           // ushort4[9*128] = 9216
#define OFF_MW  (OFF_MI + 9 * 128 * 8)          // 74752: float4[9*128]
#define OFF_ST  (OFF_MW + 9 * 128 * 16)         // 93184: 256 floats BN stats
#define SMEM_TOTAL (OFF_ST + 1024)              // 94208

template<int C, bool BNIN>
__global__ void __launch_bounds__(512, 1)
deform_mma(const float* __restrict__ x, const float* __restrict__ offs,
           const float* __restrict__ stats,
           const __nv_bfloat16* __restrict__ wsw,
           const float* __restrict__ bias, float* __restrict__ out,
           float* __restrict__ part)
{
    constexpr int CK  = C * 9;
    constexpr int NCH = CK / 32;
    extern __shared__ __align__(1024) char smem[];
    const uint32_t sbase = smem_u32(smem);
    const int tid = threadIdx.x, wid = tid >> 5, l = tid & 31;
    const int b = blockIdx.y;
    const int pbase = blockIdx.x * 128;
    const int hrow = pbase >> 7;

    const float* xb   = x + (size_t)b * C * HW;
    const float* offb = offs + (size_t)b * OFFC * HW;

    ushort4* Mi = (ushort4*)(smem + OFF_MI);
    float4*  Mw = (float4*)(smem + OFF_MW);
    float*   sst = (float*)(smem + OFF_ST);

    if (BNIN && tid < 256) sst[tid] = stats[tid];

    // bilinear metadata: 9 k x 128 px (8 split offsets summed)
    for (int i = tid; i < 9 * 128; i += 512) {
        int k = i >> 7, wpx = i & 127;
        int pixel = pbase + wpx;
        const float* oy_p = offb + (2 * k) * HW + pixel;
        const float* ox_p = offb + (2 * k + 1) * HW + pixel;
        float offy = 0.f, offx = 0.f;
        #pragma unroll
        for (int s = 0; s < 8; s++) {
            offy += oy_p[(size_t)s * OFFSPLIT];
            offx += ox_p[(size_t)s * OFFSPLIT];
        }
        float py = (float)(hrow - 1 + k / 3) + offy;
        float px_ = (float)(wpx - 1 + (k - (k / 3) * 3)) + offx;
        float fy = floorf(py), fx = floorf(px_);
        int y0 = (int)fy, x0 = (int)fx;
        float wy1 = py - fy, wx1 = px_ - fx;
        float wy0 = 1.f - wy1, wx0 = 1.f - wx1;
        bool y0v = ((unsigned)y0 < 128u);
        bool y1v = ((unsigned)(y0 + 1) < 128u);
        bool x0v = ((unsigned)x0 < 128u);
        bool x1v = ((unsigned)(x0 + 1) < 128u);
        int y0c = min(max(y0, 0), 127), y1c = min(max(y0 + 1, 0), 127);
        int x0c = min(max(x0, 0), 127), x1c = min(max(x0 + 1, 0), 127);
        Mw[i] = make_float4(y0v && x0v ? wy0 * wx0 : 0.f,
                            y0v && x1v ? wy0 * wx1 : 0.f,
                            y1v && x0v ? wy1 * wx0 : 0.f,
                            y1v && x1v ? wy1 * wx1 : 0.f);
        Mi[i] = make_ushort4((unsigned short)(y0c * 128 + x0c),
                             (unsigned short)(y0c * 128 + x1c),
                             (unsigned short)(y1c * 128 + x0c),
                             (unsigned short)(y1c * 128 + x1c));
    }
    __syncthreads();

    if (wid >= 8) {
        // ================= PRODUCER =================
        const int ptid = tid - 256;
        const int px = ptid & 127;
        const int cg = ptid >> 7;
        for (int ch = 0; ch < NCH; ++ch) {
            const int slot = ch & 1;
            if (ch >= 2) bar_sync(3 + slot, 512);
            const int h64 = slot * 64;
            // B: coalesced copy of pre-swizzled chunk image
            {
                const int o = ptid & 127, plane = ptid >> 7;
                const uint4* src = (const uint4*)(wsw +
                    ((size_t)(plane * NCH + ch) * 128 + o) * 32);
                uint4 v0 = src[0], v1 = src[1], v2 = src[2], v3 = src[3];
                char* bt = smem + (plane ? BLO_O : BHI_O);
                int base = o * 128 + h64;
                *(uint4*)(bt + SWZ128(base))      = v0;
                *(uint4*)(bt + SWZ128(base + 16)) = v1;
                *(uint4*)(bt + SWZ128(base + 32)) = v2;
                *(uint4*)(bt + SWZ128(base + 48)) = v3;
            }
            // A: bilinear gather, 16 channels per thread
            {
                int k, c0;
                if (C == 64) { k = ch >> 1; c0 = (ch & 1) * 32; }
                else         { k = ch >> 2; c0 = (ch & 3) * 32; }
                ushort4 mi = Mi[k * 128 + px];
                float4  mw = Mw[k * 128 + px];
                const int cbase = c0 + cg * 16;
                const float* xc = xb + (size_t)cbase * HW;
                uint32_t hp[8], lp[8];
                #pragma unroll
                for (int g = 0; g < 4; ++g) {
                    float s[4];
                    #pragma unroll
                    for (int cc = 0; cc < 4; ++cc) {
                        const float* p = xc + (size_t)(g * 4 + cc) * HW;
                        float t0 = p[mi.x], t1 = p[mi.y], t2 = p[mi.z], t3 = p[mi.w];
                        if (BNIN) {
                            int chn = cbase + g * 4 + cc;
                            float sc = sst[chn], sh = sst[CMID + chn];
                            t0 = fmaxf(fmaf(t0, sc, sh), 0.f);
                            t1 = fmaxf(fmaf(t1, sc, sh), 0.f);
                            t2 = fmaxf(fmaf(t2, sc, sh), 0.f);
                            t3 = fmaxf(fmaf(t3, sc, sh), 0.f);
                        }
                        s[cc] = mw.x * t0 + mw.y * t1 + mw.z * t2 + mw.w * t3;
                    }
                    #pragma unroll
                    for (int q = 0; q < 2; ++q) {
                        float s0 = s[2 * q], s1 = s[2 * q + 1];
                        uint32_t hh;
                        asm("cvt.rn.bf16x2.f32 %0, %1, %2;" : "=r"(hh) : "f"(s1), "f"(s0));
                        float h0 = __uint_as_float(hh << 16);
                        float h1 = __uint_as_float(hh & 0xFFFF0000u);
                        float l0 = s0 - h0, l1 = s1 - h1;
                        uint32_t ll;
                        asm("cvt.rn.bf16x2.f32 %0, %1, %2;" : "=r"(ll) : "f"(l1), "f"(l0));
                        hp[g * 2 + q] = hh;
                        lp[g * 2 + q] = ll;
                    }
                }
                int base = px * 128 + h64 + cg * 32;
                *(uint4*)(smem + AHI_O + SWZ128(base))      = make_uint4(hp[0], hp[1], hp[2], hp[3]);
                *(uint4*)(smem + AHI_O + SWZ128(base + 16)) = make_uint4(hp[4], hp[5], hp[6], hp[7]);
                *(uint4*)(smem + ALO_O + SWZ128(base))      = make_uint4(lp[0], lp[1], lp[2], lp[3]);
                *(uint4*)(smem + ALO_O + SWZ128(base + 16)) = make_uint4(lp[4], lp[5], lp[6], lp[7]);
            }
            bar_arrive(1 + slot, 512);
        }
        return;   // producers exit; epilogue is consumer-only
    }

    // ================= CONSUMER =================
    const int mrow = (wid & 1) * 64;
    const int ncol = (wid >> 1) * 32;

    uint32_t a_base[4], a_x[4];
    {
        int row = mrow + (l & 15);
        #pragma unroll
        for (int i = 0; i < 4; i++) {
            int r = row + i * 16;
            a_base[i] = r * 128;
            a_x[i]    = (r & 7) << 4;
        }
    }
    const uint32_t a_k = (l >> 4) * 16;
    uint32_t b_base[2], b_x[2];
    {
        int row = ncol + (l & 7) + ((l >> 4) & 1) * 8;
        #pragma unroll
        for (int jp = 0; jp < 2; jp++) {
            int r = row + jp * 16;
            b_base[jp] = r * 128;
            b_x[jp]    = (r & 7) << 4;
        }
    }
    const uint32_t b_k = ((l >> 3) & 1) * 16;

    float acc[4][4][4];
    #pragma unroll
    for (int i = 0; i < 4; i++)
        #pragma unroll
        for (int j = 0; j < 4; j++)
            #pragma unroll
            for (int q = 0; q < 4; q++) acc[i][j][q] = 0.f;

    const uint32_t sAh = sbase + AHI_O, sAl = sbase + ALO_O;
    const uint32_t sBh = sbase + BHI_O, sBl = sbase + BLO_O;

    for (int ch = 0; ch < NCH; ++ch) {
        const int slot = ch & 1;
        bar_sync(1 + slot, 512);
        const uint32_t h64 = slot * 64;
        #pragma unroll
        for (int ks = 0; ks < 2; ++ks) {
            const uint32_t ka = h64 + ks * 32 + a_k;
            const uint32_t kb = h64 + ks * 32 + b_k;
            uint32_t ah[4][4], al[4][4], bh[2][4], bl[2][4];
            #pragma unroll
            for (int i = 0; i < 4; i++)
                ldmx4(ah[i], sAh + a_base[i] + (ka ^ a_x[i]));
            #pragma unroll
            for (int jp = 0; jp < 2; jp++)
                ldmx4(bh[jp], sBh + b_base[jp] + (kb ^ b_x[jp]));
            #pragma unroll
            for (int i = 0; i < 4; i++)
                #pragma unroll
                for (int jp = 0; jp < 2; jp++) {
                    mma16816(acc[i][jp * 2],     ah[i], &bh[jp][0]);
                    mma16816(acc[i][jp * 2 + 1], ah[i], &bh[jp][2]);
                }
            #pragma unroll
            for (int jp = 0; jp < 2; jp++)
                ldmx4(bl[jp], sBl + b_base[jp] + (kb ^ b_x[jp]));
            #pragma unroll
            for (int i = 0; i < 4; i++)
                #pragma unroll
                for (int jp = 0; jp < 2; jp++) {
                    mma16816(acc[i][jp * 2],     ah[i], &bl[jp][0]);
                    mma16816(acc[i][jp * 2 + 1], ah[i], &bl[jp][2]);
                }
            #pragma unroll
            for (int i = 0; i < 4; i++)
                ldmx4(al[i], sAl + a_base[i] + (ka ^ a_x[i]));
            #pragma unroll
            for (int i = 0; i < 4; i++)
                #pragma unroll
                for (int jp = 0; jp < 2; jp++) {
                    mma16816(acc[i][jp * 2],     al[i], &bh[jp][0]);
                    mma16816(acc[i][jp * 2 + 1], al[i], &bh[jp][2]);
                }
        }
        bar_arrive(3 + slot, 512);
    }

    // ---- epilogue (consumers only): store + per-channel BN partials ----
    float* ob = out + (size_t)b * 128 * HW + pbase;
    const int m0 = mrow + (l >> 2);
    float ss[4][2], sq[4][2];
    #pragma unroll
    for (int j = 0; j < 4; j++) { ss[j][0]=ss[j][1]=sq[j][0]=sq[j][1]=0.f; }
    #pragma unroll
    for (int j = 0; j < 4; j++) {
        int n0 = ncol + j * 8 + 2 * (l & 3);
        float bi0 = __ldg(&bias[n0]), bi1 = __ldg(&bias[n0 + 1]);
        #pragma unroll
        for (int i = 0; i < 4; i++) {
            int m = m0 + i * 16;
            float v0 = acc[i][j][0] + bi0;
            float v1 = acc[i][j][1] + bi1;
            float v2 = acc[i][j][2] + bi0;
            float v3 = acc[i][j][3] + bi1;
            ob[(size_t)n0       * HW + m]     = v0;
            ob[(size_t)(n0 + 1) * HW + m]     = v1;
            ob[(size_t)n0       * HW + m + 8] = v2;
            ob[(size_t)(n0 + 1) * HW + m + 8] = v3;
            ss[j][0] += v0 + v2;  sq[j][0] += v0 * v0 + v2 * v2;
            ss[j][1] += v1 + v3;  sq[j][1] += v1 * v1 + v3 * v3;
        }
    }
    #pragma unroll
    for (int j = 0; j < 4; j++)
        #pragma unroll
        for (int low = 0; low < 2; low++)
            #pragma unroll
            for (int m = 4; m <= 16; m <<= 1) {
                ss[j][low] += __shfl_xor_sync(0xFFFFFFFFu, ss[j][low], m);
                sq[j][low] += __shfl_xor_sync(0xFFFFFFFFu, sq[j][low], m);
            }
    float* spart = (float*)(smem + OFF_MI);    // Mi dead (producers exited)
    if (l < 4) {
        #pragma unroll
        for (int j = 0; j < 4; j++)
            #pragma unroll
            for (int low = 0; low < 2; low++) {
                spart[wid * 64 + j * 16 + l * 4 + low * 2 + 0] = ss[j][low];
                spart[wid * 64 + j * 16 + l * 4 + low * 2 + 1] = sq[j][low];
            }
    }
    bar_sync(9, 256);
    {
        int ch = tid >> 1, st = tid & 1;
        int slice = ch >> 5, co = ch & 31;
        int j = co >> 3, r = (co >> 1) & 3, low = co & 1;
        int idx = j * 16 + r * 4 + low * 2 + st;
        float v = spart[(2 * slice) * 64 + idx] + spart[(2 * slice + 1) * 64 + idx];
        int bid = blockIdx.y * gridDim.x + blockIdx.x;
        part[bid * 256 + tid] = v;
    }
}

// ---------------- BN finalize: 512 block-partials -> scale/shift (128 blocks) ----------------
__global__ void bn_finalize(const float* __restrict__ part,
                            const float* __restrict__ gamma,
                            const float* __restrict__ beta,
                            float* __restrict__ stats)
{
    const int c = blockIdx.x;
    const int t = threadIdx.x;
    float sum = part[(size_t)t * 256 + 2 * c] + part[(size_t)(t + 256) * 256 + 2 * c];
    float sq  = part[(size_t)t * 256 + 2 * c + 1] + part[(size_t)(t + 256) * 256 + 2 * c + 1];
    __shared__ float s1[256], s2[256];
    s1[t] = sum; s2[t] = sq;
    __syncthreads();
    for (int st = 128; st > 0; st >>= 1) {
        if (t < st) { s1[t] += s1[t + st]; s2[t] += s2[t + st]; }
        __syncthreads();
    }
    if (t == 0) {
        const float n = (float)(BATCH * HW);
        float mean = s1[0] / n;
        float var  = s2[0] / n - mean * mean;
        float inv  = rsqrtf(var + EPS);
        float sc   = gamma[c] * inv;
        stats[c]        = sc;
        stats[CMID + c] = beta[c] - mean * sc;
    }
}

// ---------------- BN apply + ReLU (final stage only) ----------------
__global__ void bn_apply_kernel(const float* __restrict__ in,
                                const float* __restrict__ stats,
                                float* __restrict__ out)
{
    const int total4 = BATCH * CMID * HW / 4;
    int i = blockIdx.x * blockDim.x + threadIdx.x;
    if (i >= total4) return;
    int e = i * 4;
    int c = (e >> 14) & 127;
    float sc = stats[c], sh = stats[CMID + c];
    float4 v = reinterpret_cast<const float4*>(in)[i];
    v.x = fmaxf(v.x * sc + sh, 0.f);
    v.y = fmaxf(v.y * sc + sh, 0.f);
    v.z = fmaxf(v.z * sc + sh, 0.f);
    v.w = fmaxf(v.w * sc + sh, 0.f);
    reinterpret_cast<float4*>(out)[i] = v;
}

extern "C" void kernel_launch(void* const* d_in, const int* in_sizes, int n_in,
                              void* d_out, int out_size)
{
    const float* x      = (const float*)d_in[0];
    const float* w_off1 = (const float*)d_in[1];
    const float* b_off1 = (const float*)d_in[2];
    const float* w1     = (const float*)d_in[3];
    const float* b1     = (const float*)d_in[4];
    const float* g1     = (const float*)d_in[5];
    const float* be1    = (const float*)d_in[6];
    const float* w_off2 = (const float*)d_in[7];
    const float* b_off2 = (const float*)d_in[8];
    const float* w2     = (const float*)d_in[9];
    const float* b2     = (const float*)d_in[10];
    const float* g2     = (const float*)d_in[11];
    const float* be2    = (const float*)d_in[12];
    float* out = (float*)d_out;

    float *off, *t1, *t2, *stats, *part;
    __nv_bfloat16 *wsw1, *wsw2;
    cudaGetSymbolAddress((void**)&off,   g_off);
    cudaGetSymbolAddress((void**)&t1,    g_t1);
    cudaGetSymbolAddress((void**)&t2,    g_t2);
    cudaGetSymbolAddress((void**)&stats, g_stats);
    cudaGetSymbolAddress((void**)&part,  g_part);
    cudaGetSymbolAddress((void**)&wsw1,  g_wsw1);
    cudaGetSymbolAddress((void**)&wsw2,  g_wsw2);

    cudaFuncSetAttribute((const void*)deform_mma<64, false>,
                         cudaFuncAttributeMaxDynamicSharedMemorySize, SMEM_TOTAL);
    cudaFuncSetAttribute((const void*)deform_mma<128, true>,
                         cudaFuncAttributeMaxDynamicSharedMemorySize, SMEM_TOTAL);

    // merged weight prep
    prep_w_all<<<(2 * 576 * 128 + 2 * 1152 * 128 + 255) / 256, 256>>>(w1, w2, wsw1, wsw2);

    // stage 1
    conv_off6<64, false><<<dim3(16, BATCH * 8, 3), 256, 6 * 8 * 9 * 4>>>(
        x, w_off1, b_off1, stats, off);
    deform_mma<64, false><<<dim3(128, BATCH), 512, SMEM_TOTAL>>>(
        x, off, stats, wsw1, b1, t1, part);
    bn_finalize<<<128, 256>>>(part, g1, be1, stats);

    // stage 2 (consumers apply stage-1 BN+ReLU inline on raw t1)
    conv_off6<128, true><<<dim3(16, BATCH * 8, 3), 256, 6 * 16 * 9 * 4>>>(
        t1, w_off2, b_off2, stats, off);
    deform_mma<128, true><<<dim3(128, BATCH), 512, SMEM_TOTAL>>>(
        t1, off, stats, wsw2, b2, t2, part);
    bn_finalize<<<128, 256>>>(part, g2, be2, stats);
    bn_apply_kernel<<<(BATCH * CMID * HW / 4 + 255) / 256, 256>>>(t2, stats, out);
}

// round 17
// speedup vs baseline: 1.1229x; 1.0101x over previous
#include <cuda_runtime.h>
#include <cuda_bf16.h>
#include <math.h>
#include <stdint.h>

#define BATCH 4
#define HW 16384
#define HH 128
#define WW 128
#define OFFC 18
#define CMID 128
#define EPS 1e-5f
#define OFFSPLIT (BATCH * OFFC * HW)

#define SWZ128(o) ((o) ^ (((o) >> 3) & 0x70))

__device__ __forceinline__ uint32_t smem_u32(const void* p) {
    uint32_t a;
    asm("{ .reg .u64 t; cvta.to.shared.u64 t, %1; cvt.u32.u64 %0, t; }" : "=r"(a) : "l"(p));
    return a;
}
__device__ __forceinline__ void ldmx4(uint32_t* r, uint32_t addr) {
    asm volatile("ldmatrix.sync.aligned.m8n8.x4.shared.b16 {%0,%1,%2,%3}, [%4];"
                 : "=r"(r[0]), "=r"(r[1]), "=r"(r[2]), "=r"(r[3]) : "r"(addr));
}
__device__ __forceinline__ void mma16816(float* d, const uint32_t* a, const uint32_t* b) {
    asm volatile(
        "mma.sync.aligned.m16n8k16.row.col.f32.bf16.bf16.f32 "
        "{%0,%1,%2,%3}, {%4,%5,%6,%7}, {%8,%9}, {%0,%1,%2,%3};"
        : "+f"(d[0]), "+f"(d[1]), "+f"(d[2]), "+f"(d[3])
        : "r"(a[0]), "r"(a[1]), "r"(a[2]), "r"(a[3]), "r"(b[0]), "r"(b[1]));
}
__device__ __forceinline__ void bar_sync(int id, int cnt) {
    asm volatile("bar.sync %0, %1;" :: "r"(id), "r"(cnt) : "memory");
}
__device__ __forceinline__ void bar_arrive(int id, int cnt) {
    asm volatile("bar.arrive %0, %1;" :: "r"(id), "r"(cnt) : "memory");
}

// ---------------- scratch (device globals) ----------------
__device__ float g_off[8 * OFFSPLIT];            // 8-way split offset partials
__device__ float g_t1 [BATCH * CMID * HW];
__device__ float g_t2 [BATCH * CMID * HW];
__device__ float g_stats[2 * CMID];
__device__ float g_part[512 * 256];              // per-block (sum, sumsq) partials
__device__ __nv_bfloat16 g_wsw1[2 * 18 * 128 * 32];
__device__ __nv_bfloat16 g_wsw2[2 * 36 * 128 * 32];

// merged weight prep: w[o][c][k] -> wsw[plane][ch][o][e], kk = ch*32+e = k*C + c
__global__ void prep_w_all(const float* __restrict__ w1, const float* __restrict__ w2,
                           __nv_bfloat16* __restrict__ wsw1,
                           __nv_bfloat16* __restrict__ wsw2) {
    const int N1 = 2 * 576 * 128;
    const int N2 = 2 * 1152 * 128;
    int i = blockIdx.x * blockDim.x + threadIdx.x;
    if (i < N1) {
        const int C = 64, CK = 576, NCH = 18;
        int plane = i / (CK * 128);
        int rem   = i - plane * CK * 128;
        int ch = rem / (128 * 32);
        int r2 = rem - ch * 128 * 32;
        int o  = r2 >> 5, e = r2 & 31;
        int kk = ch * 32 + e;
        int k = kk / C, c = kk - k * C;
        float v = w1[(o * C + c) * 9 + k];
        __nv_bfloat16 h = __float2bfloat16(v);
        wsw1[((size_t)(plane * NCH + ch) * 128 + o) * 32 + e] =
            plane ? __float2bfloat16(v - __bfloat162float(h)) : h;
    } else if (i < N1 + N2) {
        i -= N1;
        const int C = 128, CK = 1152, NCH = 36;
        int plane = i / (CK * 128);
        int rem   = i - plane * CK * 128;
        int ch = rem / (128 * 32);
        int r2 = rem - ch * 128 * 32;
        int o  = r2 >> 5, e = r2 & 31;
        int kk = ch * 32 + e;
        int k = kk / C, c = kk - k * C;
        float v = w2[(o * C + c) * 9 + k];
        __nv_bfloat16 h = __float2bfloat16(v);
        wsw2[((size_t)(plane * NCH + ch) * 128 + o) * 32 + e] =
            plane ? __float2bfloat16(v - __bfloat162float(h)) : h;
    }
}

// ---------------- 3x3 offset conv: ALL 18 oc per block, channel-split x8 ----------------
// One block computes all 18 offset channels for its pixel tile: x slab read ONCE
// (previously 3x via the oc-group z-dim); each loaded value feeds 162 FMAs.
template<int C, bool BNIN>
__global__ void __launch_bounds__(256)
conv_off18(const float* __restrict__ x, const float* __restrict__ w,
           const float* __restrict__ bias, const float* __restrict__ stats,
           float* __restrict__ out)
{
    constexpr int CH = C / 8;
    extern __shared__ float ws[];             // [18][CH][9]
    const int b  = blockIdx.y >> 3;
    const int s  = blockIdx.y & 7;
    for (int i = threadIdx.x; i < 18 * CH * 9; i += 256) {
        int oc = i / (CH * 9);
        int r  = i - oc * (CH * 9);
        ws[i] = w[(oc * C + s * CH) * 9 + r];
    }
    __syncthreads();

    const int quad = blockIdx.x * 256 + threadIdx.x;
    const int h  = quad >> 5;                 // warp-uniform
    const int w0 = (quad & 31) << 2;
    const bool has_l = (w0 > 0);
    const bool has_r = (w0 < 124);

    const float* xb = x + ((size_t)b * C + s * CH) * HW;
    float acc[18][4];
    #pragma unroll
    for (int oc = 0; oc < 18; oc++) {
        float bv = s ? 0.f : __ldg(&bias[oc]);
        acc[oc][0] = bv; acc[oc][1] = bv; acc[oc][2] = bv; acc[oc][3] = bv;
    }

    for (int c = 0; c < CH; c++) {
        const float* xc = xb + c * HW;
        float sc = 1.f, sh = 0.f;
        if (BNIN) {
            int cg = s * CH + c;
            sc = __ldg(&stats[cg]);
            sh = __ldg(&stats[CMID + cg]);
        }
        float r[3][6];
        #pragma unroll
        for (int dy = 0; dy < 3; dy++) {
            int y = h - 1 + dy;
            if (y >= 0 && y < HH) {           // uniform branch
                const float* row = xc + y * WW + w0;
                float4 m = *(const float4*)row;
                float lf = has_l ? row[-1] : 0.f;
                float rt = has_r ? row[4]  : 0.f;
                if (BNIN) {
                    m.x = fmaxf(fmaf(m.x, sc, sh), 0.f);
                    m.y = fmaxf(fmaf(m.y, sc, sh), 0.f);
                    m.z = fmaxf(fmaf(m.z, sc, sh), 0.f);
                    m.w = fmaxf(fmaf(m.w, sc, sh), 0.f);
                    lf = has_l ? fmaxf(fmaf(lf, sc, sh), 0.f) : 0.f;
                    rt = has_r ? fmaxf(fmaf(rt, sc, sh), 0.f) : 0.f;
                }
                r[dy][0] = lf;  r[dy][1] = m.x; r[dy][2] = m.y;
                r[dy][3] = m.z; r[dy][4] = m.w; r[dy][5] = rt;
            } else {
                #pragma unroll
                for (int dx = 0; dx < 6; dx++) r[dy][dx] = 0.f;
            }
        }
        #pragma unroll
        for (int oc = 0; oc < 18; oc++) {
            const float* wc = ws + (oc * CH + c) * 9;
            #pragma unroll
            for (int dy = 0; dy < 3; dy++) {
                #pragma unroll
                for (int kx = 0; kx < 3; kx++) {
                    float wv = wc[dy * 3 + kx];
                    acc[oc][0] += wv * r[dy][kx + 0];
                    acc[oc][1] += wv * r[dy][kx + 1];
                    acc[oc][2] += wv * r[dy][kx + 2];
                    acc[oc][3] += wv * r[dy][kx + 3];
                }
            }
        }
    }
    float* outp = out + (size_t)s * OFFSPLIT;
    #pragma unroll
    for (int oc = 0; oc < 18; oc++) {
        float4 v = make_float4(acc[oc][0], acc[oc][1], acc[oc][2], acc[oc][3]);
        *reinterpret_cast<float4*>(
            &outp[((size_t)b * OFFC + oc) * HW + h * WW + w0]) = v;
    }
}

// ---------------- deformable conv: warp-specialized mma.sync bf16x3 ----------------
// 512 threads: warps 0-7 consumers, warps 8-15 producers. 2-slot ring (one 64KB
// tile-set; the two 64B row-halves are the slots). 128-px tiles, SW128.
#define AHI_O   0
#define ALO_O   16384
#define BHI_O   32768
#define BLO_O   49152
#define OFF_MI  65536                           // ushort4[9*128] = 9216
#define OFF_MW  (OFF_MI + 9 * 128 * 8)          // 74752: float4[9*128]
#define OFF_ST  (OFF_MW + 9 * 128 * 16)         // 93184: 256 floats BN stats
#define SMEM_TOTAL (OFF_ST + 1024)              // 94208

template<int C, bool BNIN>
__global__ void __launch_bounds__(512, 1)
deform_mma(const float* __restrict__ x, const float* __restrict__ offs,
           const float* __restrict__ stats,
           const __nv_bfloat16* __restrict__ wsw,
           const float* __restrict__ bias, float* __restrict__ out,
           float* __restrict__ part)
{
    constexpr int CK  = C * 9;
    constexpr int NCH = CK / 32;
    extern __shared__ __align__(1024) char smem[];
    const uint32_t sbase = smem_u32(smem);
    const int tid = threadIdx.x, wid = tid >> 5, l = tid & 31;
    const int b = blockIdx.y;
    const int pbase = blockIdx.x * 128;
    const int hrow = pbase >> 7;

    const float* xb   = x + (size_t)b * C * HW;
    const float* offb = offs + (size_t)b * OFFC * HW;

    ushort4* Mi = (ushort4*)(smem + OFF_MI);
    float4*  Mw = (float4*)(smem + OFF_MW);
    float*   sst = (float*)(smem + OFF_ST);

    if (BNIN && tid < 256) sst[tid] = stats[tid];

    // bilinear metadata: 9 k x 128 px (8 split offsets summed)
    for (int i = tid; i < 9 * 128; i += 512) {
        int k = i >> 7, wpx = i & 127;
        int pixel = pbase + wpx;
        const float* oy_p = offb + (2 * k) * HW + pixel;
        const float* ox_p = offb + (2 * k + 1) * HW + pixel;
        float offy = 0.f, offx = 0.f;
        #pragma unroll
        for (int s = 0; s < 8; s++) {
            offy += oy_p[(size_t)s * OFFSPLIT];
            offx += ox_p[(size_t)s * OFFSPLIT];
        }
        float py = (float)(hrow - 1 + k / 3) + offy;
        float px_ = (float)(wpx - 1 + (k - (k / 3) * 3)) + offx;
        float fy = floorf(py), fx = floorf(px_);
        int y0 = (int)fy, x0 = (int)fx;
        float wy1 = py - fy, wx1 = px_ - fx;
        float wy0 = 1.f - wy1, wx0 = 1.f - wx1;
        bool y0v = ((unsigned)y0 < 128u);
        bool y1v = ((unsigned)(y0 + 1) < 128u);
        bool x0v = ((unsigned)x0 < 128u);
        bool x1v = ((unsigned)(x0 + 1) < 128u);
        int y0c = min(max(y0, 0), 127), y1c = min(max(y0 + 1, 0), 127);
        int x0c = min(max(x0, 0), 127), x1c = min(max(x0 + 1, 0), 127);
        Mw[i] = make_float4(y0v && x0v ? wy0 * wx0 : 0.f,
                            y0v && x1v ? wy0 * wx1 : 0.f,
                            y1v && x0v ? wy1 * wx0 : 0.f,
                            y1v && x1v ? wy1 * wx1 : 0.f);
        Mi[i] = make_ushort4((unsigned short)(y0c * 128 + x0c),
                             (unsigned short)(y0c * 128 + x1c),
                             (unsigned short)(y1c * 128 + x0c),
                             (unsigned short)(y1c * 128 + x1c));
    }
    __syncthreads();

    if (wid >= 8) {
        // ================= PRODUCER =================
        const int ptid = tid - 256;
        const int px = ptid & 127;
        const int cg = ptid >> 7;
        for (int ch = 0; ch < NCH; ++ch) {
            const int slot = ch & 1;
            if (ch >= 2) bar_sync(3 + slot, 512);
            const int h64 = slot * 64;
            // B: coalesced copy of pre-swizzled chunk image
            {
                const int o = ptid & 127, plane = ptid >> 7;
                const uint4* src = (const uint4*)(wsw +
                    ((size_t)(plane * NCH + ch) * 128 + o) * 32);
                uint4 v0 = src[0], v1 = src[1], v2 = src[2], v3 = src[3];
                char* bt = smem + (plane ? BLO_O : BHI_O);
                int base = o * 128 + h64;
                *(uint4*)(bt + SWZ128(base))      = v0;
                *(uint4*)(bt + SWZ128(base + 16)) = v1;
                *(uint4*)(bt + SWZ128(base + 32)) = v2;
                *(uint4*)(bt + SWZ128(base + 48)) = v3;
            }
            // A: bilinear gather, 16 channels per thread
            {
                int k, c0;
                if (C == 64) { k = ch >> 1; c0 = (ch & 1) * 32; }
                else         { k = ch >> 2; c0 = (ch & 3) * 32; }
                ushort4 mi = Mi[k * 128 + px];
                float4  mw = Mw[k * 128 + px];
                const int cbase = c0 + cg * 16;
                const float* xc = xb + (size_t)cbase * HW;
                uint32_t hp[8], lp[8];
                #pragma unroll
                for (int g = 0; g < 4; ++g) {
                    float s[4];
                    #pragma unroll
                    for (int cc = 0; cc < 4; ++cc) {
                        const float* p = xc + (size_t)(g * 4 + cc) * HW;
                        float t0 = p[mi.x], t1 = p[mi.y], t2 = p[mi.z], t3 = p[mi.w];
                        if (BNIN) {
                            int chn = cbase + g * 4 + cc;
                            float sc = sst[chn], sh = sst[CMID + chn];
                            t0 = fmaxf(fmaf(t0, sc, sh), 0.f);
                            t1 = fmaxf(fmaf(t1, sc, sh), 0.f);
                            t2 = fmaxf(fmaf(t2, sc, sh), 0.f);
                            t3 = fmaxf(fmaf(t3, sc, sh), 0.f);
                        }
                        s[cc] = mw.x * t0 + mw.y * t1 + mw.z * t2 + mw.w * t3;
                    }
                    #pragma unroll
                    for (int q = 0; q < 2; ++q) {
                        float s0 = s[2 * q], s1 = s[2 * q + 1];
                        uint32_t hh;
                        asm("cvt.rn.bf16x2.f32 %0, %1, %2;" : "=r"(hh) : "f"(s1), "f"(s0));
                        float h0 = __uint_as_float(hh << 16);
                        float h1 = __uint_as_float(hh & 0xFFFF0000u);
                        float l0 = s0 - h0, l1 = s1 - h1;
                        uint32_t ll;
                        asm("cvt.rn.bf16x2.f32 %0, %1, %2;" : "=r"(ll) : "f"(l1), "f"(l0));
                        hp[g * 2 + q] = hh;
                        lp[g * 2 + q] = ll;
                    }
                }
                int base = px * 128 + h64 + cg * 32;
                *(uint4*)(smem + AHI_O + SWZ128(base))      = make_uint4(hp[0], hp[1], hp[2], hp[3]);
                *(uint4*)(smem + AHI_O + SWZ128(base + 16)) = make_uint4(hp[4], hp[5], hp[6], hp[7]);
                *(uint4*)(smem + ALO_O + SWZ128(base))      = make_uint4(lp[0], lp[1], lp[2], lp[3]);
                *(uint4*)(smem + ALO_O + SWZ128(base + 16)) = make_uint4(lp[4], lp[5], lp[6], lp[7]);
            }
            bar_arrive(1 + slot, 512);
        }
        return;   // producers exit; epilogue is consumer-only
    }

    // ================= CONSUMER =================
    const int mrow = (wid & 1) * 64;
    const int ncol = (wid >> 1) * 32;

    uint32_t a_base[4], a_x[4];
    {
        int row = mrow + (l & 15);
        #pragma unroll
        for (int i = 0; i < 4; i++) {
            int r = row + i * 16;
            a_base[i] = r * 128;
            a_x[i]    = (r & 7) << 4;
        }
    }
    const uint32_t a_k = (l >> 4) * 16;
    uint32_t b_base[2], b_x[2];
    {
        int row = ncol + (l & 7) + ((l >> 4) & 1) * 8;
        #pragma unroll
        for (int jp = 0; jp < 2; jp++) {
            int r = row + jp * 16;
            b_base[jp] = r * 128;
            b_x[jp]    = (r & 7) << 4;
        }
    }
    const uint32_t b_k = ((l >> 3) & 1) * 16;

    float acc[4][4][4];
    #pragma unroll
    for (int i = 0; i < 4; i++)
        #pragma unroll
        for (int j = 0; j < 4; j++)
            #pragma unroll
            for (int q = 0; q < 4; q++) acc[i][j][q] = 0.f;

    const uint32_t sAh = sbase + AHI_O, sAl = sbase + ALO_O;
    const uint32_t sBh = sbase + BHI_O, sBl = sbase + BLO_O;

    for (int ch = 0; ch < NCH; ++ch) {
        const int slot = ch & 1;
        bar_sync(1 + slot, 512);
        const uint32_t h64 = slot * 64;
        #pragma unroll
        for (int ks = 0; ks < 2; ++ks) {
            const uint32_t ka = h64 + ks * 32 + a_k;
            const uint32_t kb = h64 + ks * 32 + b_k;
            uint32_t ah[4][4], al[4][4], bh[2][4], bl[2][4];
            #pragma unroll
            for (int i = 0; i < 4; i++)
                ldmx4(ah[i], sAh + a_base[i] + (ka ^ a_x[i]));
            #pragma unroll
            for (int jp = 0; jp < 2; jp++)
                ldmx4(bh[jp], sBh + b_base[jp] + (kb ^ b_x[jp]));
            #pragma unroll
            for (int i = 0; i < 4; i++)
                #pragma unroll
                for (int jp = 0; jp < 2; jp++) {
                    mma16816(acc[i][jp * 2],     ah[i], &bh[jp][0]);
                    mma16816(acc[i][jp * 2 + 1], ah[i], &bh[jp][2]);
                }
            #pragma unroll
            for (int jp = 0; jp < 2; jp++)
                ldmx4(bl[jp], sBl + b_base[jp] + (kb ^ b_x[jp]));
            #pragma unroll
            for (int i = 0; i < 4; i++)
                #pragma unroll
                for (int jp = 0; jp < 2; jp++) {
                    mma16816(acc[i][jp * 2],     ah[i], &bl[jp][0]);
                    mma16816(acc[i][jp * 2 + 1], ah[i], &bl[jp][2]);
                }
            #pragma unroll
            for (int i = 0; i < 4; i++)
                ldmx4(al[i], sAl + a_base[i] + (ka ^ a_x[i]));
            #pragma unroll
            for (int i = 0; i < 4; i++)
                #pragma unroll
                for (int jp = 0; jp < 2; jp++) {
                    mma16816(acc[i][jp * 2],     al[i], &bh[jp][0]);
                    mma16816(acc[i][jp * 2 + 1], al[i], &bh[jp][2]);
                }
        }
        bar_arrive(3 + slot, 512);
    }

    // ---- epilogue (consumers only): store + per-channel BN partials ----
    float* ob = out + (size_t)b * 128 * HW + pbase;
    const int m0 = mrow + (l >> 2);
    float ss[4][2], sq[4][2];
    #pragma unroll
    for (int j = 0; j < 4; j++) { ss[j][0]=ss[j][1]=sq[j][0]=sq[j][1]=0.f; }
    #pragma unroll
    for (int j = 0; j < 4; j++) {
        int n0 = ncol + j * 8 + 2 * (l & 3);
        float bi0 = __ldg(&bias[n0]), bi1 = __ldg(&bias[n0 + 1]);
        #pragma unroll
        for (int i = 0; i < 4; i++) {
            int m = m0 + i * 16;
            float v0 = acc[i][j][0] + bi0;
            float v1 = acc[i][j][1] + bi1;
            float v2 = acc[i][j][2] + bi0;
            float v3 = acc[i][j][3] + bi1;
            ob[(size_t)n0       * HW + m]     = v0;
            ob[(size_t)(n0 + 1) * HW + m]     = v1;
            ob[(size_t)n0       * HW + m + 8] = v2;
            ob[(size_t)(n0 + 1) * HW + m + 8] = v3;
            ss[j][0] += v0 + v2;  sq[j][0] += v0 * v0 + v2 * v2;
            ss[j][1] += v1 + v3;  sq[j][1] += v1 * v1 + v3 * v3;
        }
    }
    #pragma unroll
    for (int j = 0; j < 4; j++)
        #pragma unroll
        for (int low = 0; low < 2; low++)
            #pragma unroll
            for (int m = 4; m <= 16; m <<= 1) {
                ss[j][low] += __shfl_xor_sync(0xFFFFFFFFu, ss[j][low], m);
                sq[j][low] += __shfl_xor_sync(0xFFFFFFFFu, sq[j][low], m);
            }
    float* spart = (float*)(smem + OFF_MI);    // Mi dead (producers exited)
    if (l < 4) {
        #pragma unroll
        for (int j = 0; j < 4; j++)
            #pragma unroll
            for (int low = 0; low < 2; low++) {
                spart[wid * 64 + j * 16 + l * 4 + low * 2 + 0] = ss[j][low];
                spart[wid * 64 + j * 16 + l * 4 + low * 2 + 1] = sq[j][low];
            }
    }
    bar_sync(9, 256);
    {
        int ch = tid >> 1, st = tid & 1;
        int slice = ch >> 5, co = ch & 31;
        int j = co >> 3, r = (co >> 1) & 3, low = co & 1;
        int idx = j * 16 + r * 4 + low * 2 + st;
        float v = spart[(2 * slice) * 64 + idx] + spart[(2 * slice + 1) * 64 + idx];
        int bid = blockIdx.y * gridDim.x + blockIdx.x;
        part[bid * 256 + tid] = v;
    }
}

// ---------------- BN finalize: 512 block-partials -> scale/shift (128 blocks) ----------------
__global__ void bn_finalize(const float* __restrict__ part,
                            const float* __restrict__ gamma,
                            const float* __restrict__ beta,
                            float* __restrict__ stats)
{
    const int c = blockIdx.x;
    const int t = threadIdx.x;
    float sum = part[(size_t)t * 256 + 2 * c] + part[(size_t)(t + 256) * 256 + 2 * c];
    float sq  = part[(size_t)t * 256 + 2 * c + 1] + part[(size_t)(t + 256) * 256 + 2 * c + 1];
    __shared__ float s1[256], s2[256];
    s1[t] = sum; s2[t] = sq;
    __syncthreads();
    for (int st = 128; st > 0; st >>= 1) {
        if (t < st) { s1[t] += s1[t + st]; s2[t] += s2[t + st]; }
        __syncthreads();
    }
    if (t == 0) {
        const float n = (float)(BATCH * HW);
        float mean = s1[0] / n;
        float var  = s2[0] / n - mean * mean;
        float inv  = rsqrtf(var + EPS);
        float sc   = gamma[c] * inv;
        stats[c]        = sc;
        stats[CMID + c] = beta[c] - mean * sc;
    }
}

// ---------------- BN apply + ReLU (final stage only) ----------------
__global__ void bn_apply_kernel(const float* __restrict__ in,
                                const float* __restrict__ stats,
                                float* __restrict__ out)
{
    const int total4 = BATCH * CMID * HW / 4;
    int i = blockIdx.x * blockDim.x + threadIdx.x;
    if (i >= total4) return;
    int e = i * 4;
    int c = (e >> 14) & 127;
    float sc = stats[c], sh = stats[CMID + c];
    float4 v = reinterpret_cast<const float4*>(in)[i];
    v.x = fmaxf(v.x * sc + sh, 0.f);
    v.y = fmaxf(v.y * sc + sh, 0.f);
    v.z = fmaxf(v.z * sc + sh, 0.f);
    v.w = fmaxf(v.w * sc + sh, 0.f);
    reinterpret_cast<float4*>(out)[i] = v;
}

extern "C" void kernel_launch(void* const* d_in, const int* in_sizes, int n_in,
                              void* d_out, int out_size)
{
    const float* x      = (const float*)d_in[0];
    const float* w_off1 = (const float*)d_in[1];
    const float* b_off1 = (const float*)d_in[2];
    const float* w1     = (const float*)d_in[3];
    const float* b1     = (const float*)d_in[4];
    const float* g1     = (const float*)d_in[5];
    const float* be1    = (const float*)d_in[6];
    const float* w_off2 = (const float*)d_in[7];
    const float* b_off2 = (const float*)d_in[8];
    const float* w2     = (const float*)d_in[9];
    const float* b2     = (const float*)d_in[10];
    const float* g2     = (const float*)d_in[11];
    const float* be2    = (const float*)d_in[12];
    float* out = (float*)d_out;

    float *off, *t1, *t2, *stats, *part;
    __nv_bfloat16 *wsw1, *wsw2;
    cudaGetSymbolAddress((void**)&off,   g_off);
    cudaGetSymbolAddress((void**)&t1,    g_t1);
    cudaGetSymbolAddress((void**)&t2,    g_t2);
    cudaGetSymbolAddress((void**)&stats, g_stats);
    cudaGetSymbolAddress((void**)&part,  g_part);
    cudaGetSymbolAddress((void**)&wsw1,  g_wsw1);
    cudaGetSymbolAddress((void**)&wsw2,  g_wsw2);

    cudaFuncSetAttribute((const void*)deform_mma<64, false>,
                         cudaFuncAttributeMaxDynamicSharedMemorySize, SMEM_TOTAL);
    cudaFuncSetAttribute((const void*)deform_mma<128, true>,
                         cudaFuncAttributeMaxDynamicSharedMemorySize, SMEM_TOTAL);

    // merged weight prep
    prep_w_all<<<(2 * 576 * 128 + 2 * 1152 * 128 + 255) / 256, 256>>>(w1, w2, wsw1, wsw2);

    // stage 1
    conv_off18<64, false><<<dim3(16, BATCH * 8), 256, 18 * 8 * 9 * 4>>>(
        x, w_off1, b_off1, stats, off);
    deform_mma<64, false><<<dim3(128, BATCH), 512, SMEM_TOTAL>>>(
        x, off, stats, wsw1, b1, t1, part);
    bn_finalize<<<128, 256>>>(part, g1, be1, stats);

    // stage 2 (consumers apply stage-1 BN+ReLU inline on raw t1)
    conv_off18<128, true><<<dim3(16, BATCH * 8), 256, 18 * 16 * 9 * 4>>>(
        t1, w_off2, b_off2, stats, off);
    deform_mma<128, true><<<dim3(128, BATCH), 512, SMEM_TOTAL>>>(
        t1, off, stats, wsw2, b2, t2, part);
    bn_finalize<<<128, 256>>>(part, g2, be2, stats);
    bn_apply_kernel<<<(BATCH * CMID * HW / 4 + 255) / 256, 256>>>(t2, stats, out);
}